// round 15
// baseline (speedup 1.0000x reference)
#include <cuda_runtime.h>
#include <cuda_fp16.h>
#include <math.h>
#include <stdint.h>

// Problem constants
#define Bc   2
#define Sc   2048
#define Hc   2048
#define NHc  32
#define NKVc 8
#define HDc  64
#define MQ   (Bc * Sc)          // 4096 rows
#define NQKV 3072               // fused QKV output columns (2048 q | 512 k | 512 v)

#if defined(__CUDA_ARCH__) && defined(__CUDA_ARCH_FEAT_SM103_ALL)
#define HAS_TCGEN05 1
#else
#define HAS_TCGEN05 0
#endif

// ---------------------------------------------------------------------------
// Scratch (device globals)
// ---------------------------------------------------------------------------
__device__ float  g_qkv[(size_t)MQ * NQKV];             // fused projection output
__device__ float  g_cos[(size_t)MQ * HDc];
__device__ float  g_sin[(size_t)MQ * HDc];
__device__ float  g_bc [NQKV];                          // fused bias
// fp16 hi/lo split operands
__device__ __half g_xh [(size_t)MQ * Hc],        g_xl [(size_t)MQ * Hc];
__device__ __half g_qh [(size_t)MQ * NHc * HDc], g_ql [(size_t)MQ * NHc * HDc];
__device__ __half g_kh [(size_t)MQ * NKVc * HDc], g_kl [(size_t)MQ * NKVc * HDc];
__device__ __half g_vth[(size_t)Bc * NKVc * HDc * Sc], g_vtl[(size_t)Bc * NKVc * HDc * Sc];
__device__ __half g_ath[(size_t)MQ * Hc],        g_atl[(size_t)MQ * Hc];
// transposed + fp16-split weights: [N, K] row-major
__device__ __half g_wch[(size_t)NQKV * 2048], g_wcl[(size_t)NQKV * 2048];  // fused QKV
__device__ __half g_woh[(size_t)2048 * 2048], g_wol[(size_t)2048 * 2048];

// ---------------------------------------------------------------------------
// helpers
// ---------------------------------------------------------------------------
__device__ __forceinline__ uint32_t smem_u32(const void* p) {
    uint32_t a;
    asm("{ .reg .u64 t; cvta.to.shared.u64 t, %1; cvt.u32.u64 %0, t; }" : "=r"(a) : "l"(p));
    return a;
}
__device__ __forceinline__ float fast_exp2(float x) {
    float y;
    asm("ex2.approx.ftz.f32 %0, %1;" : "=f"(y) : "f"(x));
    return y;
}
__device__ __forceinline__ void split_h(float x, __half& h, __half& l) {
    h = __float2half_rn(x);
    l = __float2half_rn(x - __half2float(h));
}

#if HAS_TCGEN05
__device__ __forceinline__ uint64_t mk_desc(uint32_t addr) {
    // SW128, version=1 (Blackwell), SBO=64, LBO=1
    return ((uint64_t)2 << 61) | ((uint64_t)1 << 46) | ((uint64_t)64 << 32) |
           ((uint64_t)1 << 16) | ((uint64_t)((addr >> 4) & 0x3FFF));
}
__device__ __forceinline__ void mma_f16(uint32_t d, uint64_t ad, uint64_t bd,
                                        uint32_t idesc, uint32_t en) {
    asm volatile(
        "{\n\t.reg .pred p;\n\t"
        "setp.ne.u32 p, %4, 0;\n\t"
        "tcgen05.mma.cta_group::1.kind::f16 [%0], %1, %2, %3, {%5, %5, %5, %5}, p;\n\t}"
        :: "r"(d), "l"(ad), "l"(bd), "r"(idesc), "r"(en), "r"(0u) : "memory");
}
__device__ __forceinline__ void mma_f16_ts(uint32_t d, uint32_t a, uint64_t bd,
                                           uint32_t idesc, uint32_t en) {
    asm volatile(
        "{\n\t.reg .pred p;\n\t"
        "setp.ne.u32 p, %4, 0;\n\t"
        "tcgen05.mma.cta_group::1.kind::f16 [%0], [%1], %2, %3, {%5, %5, %5, %5}, p;\n\t}"
        :: "r"(d), "r"(a), "l"(bd), "r"(idesc), "r"(en), "r"(0u) : "memory");
}
__device__ __forceinline__ void mbar_wait(uint32_t m, uint32_t par) {
    asm volatile(
        "{\n\t.reg .pred P;\n\t"
        "WL%=:\n\t"
        "mbarrier.try_wait.parity.acquire.cta.shared::cta.b64 P, [%0], %1, 0x989680;\n\t"
        "@!P bra WL%=;\n\t}"
        :: "r"(m), "r"(par) : "memory");
}
__device__ __forceinline__ void ldtm32(uint32_t* r, uint32_t addr) {
    asm volatile(
        "tcgen05.ld.sync.aligned.32x32b.x32.b32 "
        "{%0, %1, %2, %3, %4, %5, %6, %7, "
        " %8, %9, %10, %11, %12, %13, %14, %15, "
        " %16, %17, %18, %19, %20, %21, %22, %23, "
        " %24, %25, %26, %27, %28, %29, %30, %31}, [%32];"
        : "=r"(r[0]),  "=r"(r[1]),  "=r"(r[2]),  "=r"(r[3]),
          "=r"(r[4]),  "=r"(r[5]),  "=r"(r[6]),  "=r"(r[7]),
          "=r"(r[8]),  "=r"(r[9]),  "=r"(r[10]), "=r"(r[11]),
          "=r"(r[12]), "=r"(r[13]), "=r"(r[14]), "=r"(r[15]),
          "=r"(r[16]), "=r"(r[17]), "=r"(r[18]), "=r"(r[19]),
          "=r"(r[20]), "=r"(r[21]), "=r"(r[22]), "=r"(r[23]),
          "=r"(r[24]), "=r"(r[25]), "=r"(r[26]), "=r"(r[27]),
          "=r"(r[28]), "=r"(r[29]), "=r"(r[30]), "=r"(r[31])
        : "r"(addr));
}
__device__ __forceinline__ void sttm32(uint32_t addr, const uint32_t* r) {
    asm volatile(
        "tcgen05.st.sync.aligned.32x32b.x32.b32 [%0], "
        "{%1, %2, %3, %4, %5, %6, %7, %8, "
        " %9, %10, %11, %12, %13, %14, %15, %16, "
        " %17, %18, %19, %20, %21, %22, %23, %24, "
        " %25, %26, %27, %28, %29, %30, %31, %32};"
        :: "r"(addr),
           "r"(r[0]),  "r"(r[1]),  "r"(r[2]),  "r"(r[3]),
           "r"(r[4]),  "r"(r[5]),  "r"(r[6]),  "r"(r[7]),
           "r"(r[8]),  "r"(r[9]),  "r"(r[10]), "r"(r[11]),
           "r"(r[12]), "r"(r[13]), "r"(r[14]), "r"(r[15]),
           "r"(r[16]), "r"(r[17]), "r"(r[18]), "r"(r[19]),
           "r"(r[20]), "r"(r[21]), "r"(r[22]), "r"(r[23]),
           "r"(r[24]), "r"(r[25]), "r"(r[26]), "r"(r[27]),
           "r"(r[28]), "r"(r[29]), "r"(r[30]), "r"(r[31])
        : "memory");
}
__device__ __forceinline__ void sttm16(uint32_t addr, const uint32_t* r) {
    asm volatile(
        "tcgen05.st.sync.aligned.32x32b.x16.b32 [%0], "
        "{%1, %2, %3, %4, %5, %6, %7, %8, "
        " %9, %10, %11, %12, %13, %14, %15, %16};"
        :: "r"(addr),
           "r"(r[0]),  "r"(r[1]),  "r"(r[2]),  "r"(r[3]),
           "r"(r[4]),  "r"(r[5]),  "r"(r[6]),  "r"(r[7]),
           "r"(r[8]),  "r"(r[9]),  "r"(r[10]), "r"(r[11]),
           "r"(r[12]), "r"(r[13]), "r"(r[14]), "r"(r[15])
        : "memory");
}
#endif

// ---------------------------------------------------------------------------
// mRoPE cos/sin table
// ---------------------------------------------------------------------------
__global__ void cossin_kernel(const int* __restrict__ pos,
                              float* __restrict__ cosb,
                              float* __restrict__ sinb) {
    int idx = blockIdx.x * blockDim.x + threadIdx.x;
    if (idx >= Bc * Sc * HDc) return;
    int d  = idx & 63;
    int bs = idx >> 6;
    int i  = d & 31;
    int sec = (i < 16) ? 0 : 1;
    float p = (float)pos[sec * (Bc * Sc) + bs];
    float inv_freq = exp2f(-0.6228615177913804f * (float)i);
    float ang = p * inv_freq;
    float s, c;
    sincosf(ang, &s, &c);
    cosb[idx] = c;
    sinb[idx] = s;
}

// ---------------------------------------------------------------------------
// x -> fp16 hi/lo split
// ---------------------------------------------------------------------------
__global__ void xsplit_kernel(const float* __restrict__ X,
                              __half* __restrict__ Xh, __half* __restrict__ Xl,
                              int n4) {
    int idx = blockIdx.x * blockDim.x + threadIdx.x;
    if (idx >= n4) return;
    float4 v = ((const float4*)X)[idx];
    __half h, l;
    split_h(v.x, h, l); Xh[idx*4+0] = h; Xl[idx*4+0] = l;
    split_h(v.y, h, l); Xh[idx*4+1] = h; Xl[idx*4+1] = l;
    split_h(v.z, h, l); Xh[idx*4+2] = h; Xl[idx*4+2] = l;
    split_h(v.w, h, l); Xh[idx*4+3] = h; Xl[idx*4+3] = l;
}

// ---------------------------------------------------------------------------
// bias concat: [bq | bk | bv] -> bc[3072]
// ---------------------------------------------------------------------------
__global__ void bcat_kernel(const float* __restrict__ bq, const float* __restrict__ bk,
                            const float* __restrict__ bv, float* __restrict__ bc) {
    int i = blockIdx.x * 256 + threadIdx.x;
    if (i < 2048)      bc[i] = bq[i];
    else if (i < 2560) bc[i] = bk[i - 2048];
    else if (i < 3072) bc[i] = bv[i - 2560];
}

// ---------------------------------------------------------------------------
// RoPE + fp16 split from fused qkv buffer (row stride NQKV, column offset)
// ---------------------------------------------------------------------------
__global__ void rope_split_kernel(const float* __restrict__ X, int coloff,
                                  const float* __restrict__ cosb,
                                  const float* __restrict__ sinb,
                                  __half* __restrict__ Xh, __half* __restrict__ Xl,
                                  int nheads, float scale, int total_pairs) {
    int idx = blockIdx.x * blockDim.x + threadIdx.x;
    if (idx >= total_pairs) return;
    int d    = idx & 31;
    int rest = idx >> 5;                    // bs*nheads + h
    int bs   = rest / nheads;
    int h    = rest - bs * nheads;
    const float* p  = X + (size_t)bs * NQKV + coloff + h * HDc;
    const float* cb = cosb + (size_t)bs * HDc;
    const float* sb = sinb + (size_t)bs * HDc;
    float x1 = p[d], x2 = p[d + 32];
    float y1 = (x1 * cb[d]      - x2 * sb[d])      * scale;
    float y2 = (x2 * cb[d + 32] + x1 * sb[d + 32]) * scale;
    __half hh, ll;
    split_h(y1, hh, ll);
    Xh[(size_t)rest * HDc + d] = hh;  Xl[(size_t)rest * HDc + d] = ll;
    split_h(y2, hh, ll);
    Xh[(size_t)rest * HDc + d + 32] = hh;  Xl[(size_t)rest * HDc + d + 32] = ll;
}

// ---------------------------------------------------------------------------
// Weight transpose + fp16 hi/lo split: W[K,N] -> Th[N,K], Tl[N,K]
// ---------------------------------------------------------------------------
__global__ void wconv_kernel(const float* __restrict__ W,
                             __half* __restrict__ Th, __half* __restrict__ Tl,
                             int K, int N) {
    __shared__ float t[32][33];
    int n0 = blockIdx.x * 32, k0 = blockIdx.y * 32;
    int c = threadIdx.x, r0 = threadIdx.y;          // block (32,8)
    #pragma unroll
    for (int i = 0; i < 4; i++) {
        int kk = r0 + i * 8;
        t[kk][c] = W[(size_t)(k0 + kk) * N + n0 + c];
    }
    __syncthreads();
    #pragma unroll
    for (int i = 0; i < 4; i++) {
        int nn = r0 + i * 8;
        float v = t[c][nn];
        __half h, l;
        split_h(v, h, l);
        size_t o = (size_t)(n0 + nn) * K + k0 + c;
        Th[o] = h;
        Tl[o] = l;
    }
}

// ---------------------------------------------------------------------------
// V transpose + split from fused qkv: qkv[.., 2560 + kv*64 + d] -> vt[b,kv,d,s]
// ---------------------------------------------------------------------------
__global__ void vtrans_kernel(const float* __restrict__ QKV,
                              __half* __restrict__ VTh, __half* __restrict__ VTl) {
    __shared__ float t[32][33];
    int s0 = blockIdx.x * 32, d0 = blockIdx.y * 32;
    int bkv = blockIdx.z;
    int b = bkv >> 3, kv = bkv & 7;
    int c = threadIdx.x, r0 = threadIdx.y;   // block (32,8)
    #pragma unroll
    for (int i = 0; i < 4; i++) {
        int ss = r0 + i * 8;
        t[ss][c] = QKV[(size_t)(b * Sc + s0 + ss) * NQKV + 2560 + kv * HDc + d0 + c];
    }
    __syncthreads();
    #pragma unroll
    for (int i = 0; i < 4; i++) {
        int dd = r0 + i * 8;
        __half h, l;
        split_h(t[c][dd], h, l);
        size_t o = ((size_t)bkv * HDc + d0 + dd) * Sc + s0 + c;
        VTh[o] = h;
        VTl[o] = l;
    }
}

// ---------------------------------------------------------------------------
// fp16x3 GEMM, 128x256 CTA tile: C = A @ Bt^T   (unchanged from R9)
// ---------------------------------------------------------------------------
#define GEMM_THREADS 256
#define SM_TMEMPTR 0
#define SM_MBAR    16
#define SM_TILES   1024
#define GTILE_A    16384            // 128 rows x 128 bytes (64 fp16)
// buffer layout: Ah @0 | Al @16384 | Bh @32768 | Bl @65536  (96KB)
#define GBUF_B     98304
#define SM_GTOTAL  (SM_TILES + 2 * GBUF_B)   // 197632; epilogue reuses tiles

__global__ __launch_bounds__(GEMM_THREADS, 1)
void tc_gemm(const __half* __restrict__ Ah, const __half* __restrict__ Al,
             const __half* __restrict__ Bh, const __half* __restrict__ Bl,
             const float* __restrict__ bias, float* __restrict__ C,
             int N, int K) {
    extern __shared__ char sm[];
    int tid = threadIdx.x;
    int m0 = blockIdx.y * 128, n0 = blockIdx.x * 256;

#if HAS_TCGEN05
    uint32_t sb = smem_u32(sm);
    if (tid == 0) {
        asm volatile("mbarrier.init.shared.b64 [%0], 1;" :: "r"(sb + SM_MBAR)     : "memory");
        asm volatile("mbarrier.init.shared.b64 [%0], 1;" :: "r"(sb + SM_MBAR + 8) : "memory");
    }
    if (tid < 32) {
        asm volatile("tcgen05.alloc.cta_group::1.sync.aligned.shared::cta.b32 [%0], %1;"
                     :: "r"(sb + SM_TMEMPTR), "r"(256u) : "memory");
        asm volatile("tcgen05.relinquish_alloc_permit.cta_group::1.sync.aligned;");
    }
    __syncthreads();
    uint32_t tmem;
    asm volatile("ld.shared.b32 %0, [%1];" : "=r"(tmem) : "r"(sb + SM_TMEMPTR));

    const uint32_t idesc = (1u << 4) | (32u << 17) | (8u << 24);  // f16, N=256, M=128
    const int NC = K >> 6;                                        // 64-wide K chunks

    auto ldg_tiles = [&](int k0, float4* ra, float4* rb) {
        #pragma unroll
        for (int i2 = 0; i2 < 4; i2++) {           // A: 128 rows
            int idx = tid + i2 * 256;
            int r = idx >> 3, c8 = idx & 7;
            size_t ga = (size_t)(m0 + r) * K + k0 + c8 * 8;
            ra[i2 * 2 + 0] = *(const float4*)(Ah + ga);
            ra[i2 * 2 + 1] = *(const float4*)(Al + ga);
        }
        #pragma unroll
        for (int i2 = 0; i2 < 8; i2++) {           // B: 256 rows
            int idx = tid + i2 * 256;
            int r = idx >> 3, c8 = idx & 7;
            size_t gb = (size_t)(n0 + r) * K + k0 + c8 * 8;
            rb[i2 * 2 + 0] = *(const float4*)(Bh + gb);
            rb[i2 * 2 + 1] = *(const float4*)(Bl + gb);
        }
    };
    auto sts_tiles = [&](int buf, const float4* ra, const float4* rb) {
        char* base = sm + SM_TILES + (size_t)buf * GBUF_B;
        #pragma unroll
        for (int i2 = 0; i2 < 4; i2++) {
            int idx = tid + i2 * 256;
            int r = idx >> 3, c8 = idx & 7;
            uint32_t off = (uint32_t)(r * 128 + c8 * 16);
            off ^= (off >> 3) & 0x70;
            *(float4*)(base + off)           = ra[i2 * 2 + 0];
            *(float4*)(base + GTILE_A + off) = ra[i2 * 2 + 1];
        }
        #pragma unroll
        for (int i2 = 0; i2 < 8; i2++) {
            int idx = tid + i2 * 256;
            int r = idx >> 3, c8 = idx & 7;
            uint32_t off = (uint32_t)(r * 128 + c8 * 16);
            off ^= (off >> 3) & 0x70;
            *(float4*)(base + 32768 + off) = rb[i2 * 2 + 0];
            *(float4*)(base + 65536 + off) = rb[i2 * 2 + 1];
        }
    };

    {   // prologue: chunk 0 straight to smem
        float4 ra[8], rb[16];
        ldg_tiles(0, ra, rb);
        sts_tiles(0, ra, rb);
    }
    int ph0 = 0, ph1 = 0;
    for (int c = 0; c < NC; ++c) {
        int cur = c & 1;
        __syncthreads();   // tiles for chunk c visible
        if (tid == 0) {
            asm volatile("fence.proxy.async.shared::cta;" ::: "memory");
            uint32_t tb = sb + SM_TILES + (uint32_t)cur * GBUF_B;
            uint64_t ahd = mk_desc(tb);
            uint64_t ald = mk_desc(tb + GTILE_A);
            uint64_t bhd = mk_desc(tb + 32768);
            uint64_t bld = mk_desc(tb + 65536);
            #pragma unroll
            for (int ks = 0; ks < 4; ++ks) {           // 16 fp16 per step
                uint32_t en0 = (c == 0 && ks == 0) ? 0u : 1u;
                mma_f16(tmem, ahd + ks * 2, bhd + ks * 2, idesc, en0);
                mma_f16(tmem, ahd + ks * 2, bld + ks * 2, idesc, 1u);
                mma_f16(tmem, ald + ks * 2, bhd + ks * 2, idesc, 1u);
            }
            asm volatile(
                "tcgen05.commit.cta_group::1.mbarrier::arrive::one.shared::cluster.b64 [%0];"
                :: "r"(sb + SM_MBAR + (uint32_t)cur * 8) : "memory");
        }
        if (c + 1 < NC) {
            int nxt = cur ^ 1;
            float4 ra[8], rb[16];
            ldg_tiles((c + 1) << 6, ra, rb);   // LDG overlaps MMA + wait
            if (c >= 1) {
                mbar_wait(sb + SM_MBAR + (uint32_t)nxt * 8, nxt ? ph1 : ph0);
                if (nxt) ph1 ^= 1; else ph0 ^= 1;
            }
            sts_tiles(nxt, ra, rb);
        }
    }
    {
        int last = (NC - 1) & 1;
        mbar_wait(sb + SM_MBAR + (uint32_t)last * 8, last ? ph1 : ph0);
    }
    asm volatile("tcgen05.fence::after_thread_sync;" ::: "memory");
    __syncthreads();

    // epilogue: 8 col-groups of 32 (stage reuses tile smem)
    float* stage = (float*)(sm + SM_TILES);
    int wid = tid >> 5, lid = tid & 31;
    for (int g = 0; g < 8; ++g) {
        if (tid < 128) {
            uint32_t d[32];
            ldtm32(d, tmem + (uint32_t)g * 32);
            asm volatile("tcgen05.wait::ld.sync.aligned;" ::: "memory");
            int row = wid * 32 + lid;
            #pragma unroll
            for (int j = 0; j < 32; ++j)
                stage[row * 33 + j] = __uint_as_float(d[j]);
        }
        __syncthreads();
        #pragma unroll
        for (int i = 0; i < 4; ++i) {
            int rr = (tid >> 3) + i * 32;
            int c4 = tid & 7;
            float x0 = stage[rr * 33 + c4 * 4 + 0];
            float x1 = stage[rr * 33 + c4 * 4 + 1];
            float x2 = stage[rr * 33 + c4 * 4 + 2];
            float x3 = stage[rr * 33 + c4 * 4 + 3];
            int n = n0 + g * 32 + c4 * 4;
            if (bias) {
                x0 += bias[n + 0]; x1 += bias[n + 1];
                x2 += bias[n + 2]; x3 += bias[n + 3];
            }
            *(float4*)(C + (size_t)(m0 + rr) * N + n) = make_float4(x0, x1, x2, x3);
        }
        __syncthreads();
    }

    if (tid < 32) {
        asm volatile("tcgen05.dealloc.cta_group::1.sync.aligned.b32 %0, %1;"
                     :: "r"(tmem), "r"(256u));
    }
#else
    // FFMA fallback (plain sm_103 pass; GB300 loads the sm_103a cubin)
    float (*As)[128] = (float (*)[128])(sm);
    float (*Bs)[128] = (float (*)[128])(sm + 8192);
    int tcol = tid & 15;
    int trow = tid >> 4;
    for (int nh = 0; nh < 2; nh++) {        // two 128-col halves of the 256 tile
        int nb = n0 + nh * 128;
        float acc[8][8];
        #pragma unroll
        for (int i = 0; i < 8; i++)
            #pragma unroll
            for (int j = 0; j < 8; j++) acc[i][j] = 0.f;
        for (int k0 = 0; k0 < K; k0 += 16) {
            for (int idx = tid; idx < 512; idx += 256) {
                int r  = idx >> 2;
                int c4 = idx & 3;
                #pragma unroll
                for (int e = 0; e < 4; e++) {
                    int kk = c4 * 4 + e;
                    size_t ga = (size_t)(m0 + r) * K + k0 + kk;
                    size_t gb = (size_t)(nb + r) * K + k0 + kk;
                    As[kk][r] = __half2float(Ah[ga]) + __half2float(Al[ga]);
                    Bs[kk][r] = __half2float(Bh[gb]) + __half2float(Bl[gb]);
                }
            }
            __syncthreads();
            #pragma unroll
            for (int kk = 0; kk < 16; kk++) {
                float ra[8], rb[8];
                *(float4*)&ra[0] = *(const float4*)&As[kk][trow * 8];
                *(float4*)&ra[4] = *(const float4*)&As[kk][trow * 8 + 4];
                *(float4*)&rb[0] = *(const float4*)&Bs[kk][tcol * 8];
                *(float4*)&rb[4] = *(const float4*)&Bs[kk][tcol * 8 + 4];
                #pragma unroll
                for (int i = 0; i < 8; i++)
                    #pragma unroll
                    for (int j = 0; j < 8; j++)
                        acc[i][j] = fmaf(ra[i], rb[j], acc[i][j]);
            }
            __syncthreads();
        }
        #pragma unroll
        for (int i = 0; i < 8; i++) {
            int m = m0 + trow * 8 + i;
            #pragma unroll
            for (int jj = 0; jj < 8; jj++) {
                int n = nb + tcol * 8 + jj;
                float v = acc[i][jj];
                if (bias) v += bias[n];
                C[(size_t)m * N + n] = v;
            }
        }
        __syncthreads();
    }
#endif
}

// ---------------------------------------------------------------------------
// Tensor-core causal GQA attention, LEAN 2-CTA/SM + split KV tail.
// P uses fp16-hi ONLY (p in (0,1] -> hi carries >=11 bits; PV = 2 passes:
// Ph*Vh + Ph*Vl). QK stays 3-pass (errors there get exponentiated).
//  TMEM: S @0 (128 f32; Ph overlays @0..63 after read) | O @128
// ---------------------------------------------------------------------------
#define ATT_THREADS 128
#define AS_TMEM   0
#define AS_MQK    16
#define AS_MPV    24
#define AS_Q      1024               // Qh 16K | Ql 16K
#define AS_KV     (AS_Q + 32768)     // Kh 16K | Kl 16K | Vh 2x8K | Vl 2x8K
#define AS_TOTAL  (AS_KV + 65536 + 64)   // ~99KB -> 2 CTAs/SM

__global__ __launch_bounds__(ATT_THREADS, 2)
void attn_tc(const __half* __restrict__ QH, const __half* __restrict__ QL,
             const __half* __restrict__ KH, const __half* __restrict__ KL,
             const __half* __restrict__ VTH, const __half* __restrict__ VTL,
             __half* __restrict__ ATH, __half* __restrict__ ATL) {
    extern __shared__ char sm[];
    int tid = threadIdx.x;
    int qb = 15 - (int)blockIdx.x;          // big tiles first
    int hd = blockIdx.y, b = blockIdx.z;
    int khead = hd >> 2;

#if HAS_TCGEN05
    uint32_t sb = smem_u32(sm);
    if (tid == 0) {
        asm volatile("mbarrier.init.shared.b64 [%0], 1;" :: "r"(sb + AS_MQK) : "memory");
        asm volatile("mbarrier.init.shared.b64 [%0], 1;" :: "r"(sb + AS_MPV) : "memory");
    }
    if (tid < 32) {
        asm volatile("tcgen05.alloc.cta_group::1.sync.aligned.shared::cta.b32 [%0], %1;"
                     :: "r"(sb + AS_TMEM), "r"(256u) : "memory");
        asm volatile("tcgen05.relinquish_alloc_permit.cta_group::1.sync.aligned;");
    }
    __syncthreads();
    uint32_t tmem;
    asm volatile("ld.shared.b32 %0, [%1];" : "=r"(tmem) : "r"(sb + AS_TMEM));

    const uint32_t IDQK = (1u << 4) | (16u << 17) | (8u << 24);  // f16 M128 N128
    const uint32_t IDPV = (1u << 4) | (8u  << 17) | (8u << 24);  // f16 M128 N64
    const uint32_t TM_O = 128;

    // ---- Q tile (once): 2048 f4 over 128 threads ----
    #pragma unroll
    for (int i2 = 0; i2 < 8; i2++) {
        int idx = tid + i2 * 128;            // 0..1023
        int r = idx >> 3, c8 = idx & 7;
        uint32_t off = (uint32_t)(r * 128 + c8 * 16);
        off ^= (off >> 3) & 0x70;
        size_t go = (((size_t)(b * Sc + qb * 128 + r)) * NHc + hd) * HDc + c8 * 8;
        *(float4*)(sm + AS_Q + off)         = *(const float4*)(QH + go);
        *(float4*)(sm + AS_Q + 16384 + off) = *(const float4*)(QL + go);
    }

    // K loader: straight to smem (8 f4 pairs per thread)
    auto load_k = [&](int kbase) {
        char* base = sm + AS_KV;
        #pragma unroll
        for (int i2 = 0; i2 < 8; i2++) {             // K: 128 rows x 64 fp16
            int idx = tid + i2 * 128;
            int r = idx >> 3, c8 = idx & 7;
            uint32_t off = (uint32_t)(r * 128 + c8 * 16);
            off ^= (off >> 3) & 0x70;
            size_t go = (((size_t)(b * Sc + kbase + r)) * NKVc + khead) * HDc + c8 * 8;
            *(float4*)(base + off)         = *(const float4*)(KH + go);
            *(float4*)(base + 16384 + off) = *(const float4*)(KL + go);
        }
    };
    // V: register-staged (ldg then sts after the buffer frees)
    auto ldg_v = [&](int kbase, float4* rv) {
        #pragma unroll
        for (int i2 = 0; i2 < 8; i2++) {             // V^T: 64 d-rows x 128 keys
            int idx = tid + i2 * 128;
            int d = idx >> 4, c8 = idx & 15;
            size_t go = ((size_t)(b * NKVc + khead) * HDc + d) * Sc + kbase + c8 * 8;
            rv[i2 * 2 + 0] = *(const float4*)(VTH + go);
            rv[i2 * 2 + 1] = *(const float4*)(VTL + go);
        }
    };
    auto sts_v = [&](const float4* rv) {
        char* base = sm + AS_KV;
        #pragma unroll
        for (int i2 = 0; i2 < 8; i2++) {
            int idx = tid + i2 * 128;
            int d = idx >> 4, c8 = idx & 15;
            int sub = c8 >> 3;
            uint32_t off = (uint32_t)(d * 128 + (c8 & 7) * 16);
            off ^= (off >> 3) & 0x70;
            *(float4*)(base + 32768 + sub * 8192 + off) = rv[i2 * 2 + 0];
            *(float4*)(base + 49152 + sub * 8192 + off) = rv[i2 * 2 + 1];
        }
    };

    // QK for current KV buffer -> S @ tmem, commit MQK
    auto issue_qk = [&]() {
        uint32_t kvb = sb + AS_KV;
        uint64_t qhd = mk_desc(sb + AS_Q);
        uint64_t qld = mk_desc(sb + AS_Q + 16384);
        uint64_t khd = mk_desc(kvb);
        uint64_t kld = mk_desc(kvb + 16384);
        #pragma unroll
        for (int ks = 0; ks < 4; ks++) {
            mma_f16(tmem, qhd + ks * 2, khd + ks * 2, IDQK, ks == 0 ? 0u : 1u);
            mma_f16(tmem, qhd + ks * 2, kld + ks * 2, IDQK, 1u);
            mma_f16(tmem, qld + ks * 2, khd + ks * 2, IDQK, 1u);
        }
        asm volatile(
            "tcgen05.commit.cta_group::1.mbarrier::arrive::one.shared::cluster.b64 [%0];"
            :: "r"(sb + AS_MQK) : "memory");
    };

    {   // prologue: KV(0) fully to smem
        load_k(0);
        float4 rv[16];
        ldg_v(0, rv);
        sts_v(rv);
    }
    __syncthreads();
    if (tid == 0) {
        asm volatile("fence.proxy.async.shared::cta;" ::: "memory");
        issue_qk();
    }

    float m_run = -1e30f, l_run = 0.f;
    uint32_t warp_off = ((uint32_t)(tid >> 5)) << 21;
    int row = tid;

    for (int i = 0; i <= qb; i++) {
        // ---- softmax(i): wait QK(i) ----
        mbar_wait(sb + AS_MQK, i & 1);
        asm volatile("tcgen05.fence::after_thread_sync;" ::: "memory");

        float s[128];
        float mx = m_run;
        #pragma unroll
        for (int ch = 0; ch < 4; ch++) {
            uint32_t r32[32];
            ldtm32(r32, tmem + (uint32_t)ch * 32);
            asm volatile("tcgen05.wait::ld.sync.aligned;" ::: "memory");
            #pragma unroll
            for (int j = 0; j < 32; j++) {
                int key = ch * 32 + j;
                float sv = (i == qb && key > row) ? -1e30f : __uint_as_float(r32[j]);
                s[key] = sv;
                mx = fmaxf(mx, sv);
            }
        }
        float corr = fast_exp2(m_run - mx);
        if (i > 0) {
            bool need = !__all_sync(0xffffffffu, mx == m_run);
            if (need) {
                #pragma unroll
                for (int g = 0; g < 2; g++) {
                    uint32_t o32[32];
                    ldtm32(o32, tmem + TM_O + (uint32_t)g * 32);
                    asm volatile("tcgen05.wait::ld.sync.aligned;" ::: "memory");
                    #pragma unroll
                    for (int j = 0; j < 32; j++)
                        o32[j] = __float_as_uint(__uint_as_float(o32[j]) * corr);
                    sttm32(tmem + TM_O + (uint32_t)g * 32 + warp_off, o32);
                }
            }
        } else {
            corr = 0.f;
        }

        // P = exp2(s - mx); fp16-hi only (p in (0,1]); overlay S cols 0..63
        float sum = 0.f;
        #pragma unroll
        for (int ch = 0; ch < 4; ch++) {
            uint32_t phw[16];
            #pragma unroll
            for (int j = 0; j < 16; j++) {
                float p0 = fast_exp2(s[ch * 32 + j * 2]     - mx);
                float p1 = fast_exp2(s[ch * 32 + j * 2 + 1] - mx);
                sum += p0 + p1;
                __half2 hp = __floats2half2_rn(p0, p1);
                phw[j] = *(uint32_t*)&hp;
            }
            sttm16(tmem + (uint32_t)ch * 16 + warp_off, phw);        // Ph @0..63
        }
        asm volatile("tcgen05.wait::st.sync.aligned;" ::: "memory");
        asm volatile("tcgen05.fence::before_thread_sync;" ::: "memory");

        l_run = l_run * corr + sum;
        m_run = mx;
        __syncthreads();   // all warps' P written

        // ---- PV(i): 2 passes (Ph*Vh + Ph*Vl) ----
        if (tid == 0) {
            asm volatile("tcgen05.fence::after_thread_sync;" ::: "memory");
            uint32_t kvb = sb + AS_KV;
            #pragma unroll
            for (int kk = 0; kk < 8; kk++) {             // 16 keys per step
                int sub = kk >> 2, ks = kk & 3;
                uint64_t vh = mk_desc(kvb + 32768 + (uint32_t)sub * 8192) + ks * 2;
                uint64_t vl = mk_desc(kvb + 49152 + (uint32_t)sub * 8192) + ks * 2;
                uint32_t ah = tmem + (uint32_t)kk * 8;
                mma_f16_ts(tmem + TM_O, ah, vh, IDPV, (i == 0 && kk == 0) ? 0u : 1u);
                mma_f16_ts(tmem + TM_O, ah, vl, IDPV, 1u);
            }
            asm volatile(
                "tcgen05.commit.cta_group::1.mbarrier::arrive::one.shared::cluster.b64 [%0];"
                :: "r"(sb + AS_MPV) : "memory");
        }

        if (i + 1 <= qb) {
            // K(i+1) direct to smem (K(i) consumed by QK(i)); overlaps PV(i).
            load_k((i + 1) * 128);
            // V(i+1) into registers: LDG latency overlaps PV(i).
            float4 rv[16];
            ldg_v((i + 1) * 128, rv);
            mbar_wait(sb + AS_MPV, i & 1);   // V(i) consumed by PV(i)
            sts_v(rv);
            __syncthreads();
            if (tid == 0) {
                asm volatile("fence.proxy.async.shared::cta;" ::: "memory");
                issue_qk();
            }
        } else {
            mbar_wait(sb + AS_MPV, i & 1);
        }
    }

    // ---- epilogue: O/l -> fp16 hi/lo att (PV(qb) already waited) ----
    asm volatile("tcgen05.fence::after_thread_sync;" ::: "memory");
    {
        float inv_l = 1.0f / l_run;
        size_t obase = ((size_t)(b * Sc + qb * 128 + row)) * (NHc * HDc) + (size_t)hd * HDc;
        #pragma unroll
        for (int g = 0; g < 2; g++) {
            uint32_t o32[32];
            ldtm32(o32, tmem + TM_O + (uint32_t)g * 32);
            asm volatile("tcgen05.wait::ld.sync.aligned;" ::: "memory");
            #pragma unroll
            for (int j = 0; j < 32; j += 2) {
                float v0 = __uint_as_float(o32[j])     * inv_l;
                float v1 = __uint_as_float(o32[j + 1]) * inv_l;
                __half h0, l0, h1, l1;
                split_h(v0, h0, l0);
                split_h(v1, h1, l1);
                *(__half2*)(ATH + obase + g * 32 + j) = __halves2half2(h0, h1);
                *(__half2*)(ATL + obase + g * 32 + j) = __halves2half2(l0, l1);
            }
        }
    }
    __syncthreads();
    if (tid < 32) {
        asm volatile("tcgen05.dealloc.cta_group::1.sync.aligned.b32 %0, %1;"
                     :: "r"(tmem), "r"(256u));
    }
#else
    // fp32 flash fallback (plain sm_103 pass only)
    float* Ks = (float*)(sm);
    float* Vs = (float*)(sm + 128 * 64 * 4);
    int row = tid & 127;
    int qi = qb * 128 + row;
    float q[HDc], o[HDc];
    float m = -1e30f, l = 0.f;
    if (tid < 128) {
        #pragma unroll
        for (int d = 0; d < HDc; d++) {
            size_t go = (((size_t)(b * Sc + qi)) * NHc + hd) * HDc + d;
            q[d] = __half2float(QH[go]) + __half2float(QL[go]);
            o[d] = 0.f;
        }
    }
    for (int kt = 0; kt <= qb; kt++) {
        int kbase = kt * 128;
        __syncthreads();
        for (int idx = tid; idx < 128 * 64; idx += ATT_THREADS) {
            int r = idx >> 6, d = idx & 63;
            size_t go = (((size_t)(b * Sc + kbase + r)) * NKVc + khead) * HDc + d;
            Ks[r * 64 + d] = __half2float(KH[go]) + __half2float(KL[go]);
            size_t gv = ((size_t)(b * NKVc + khead) * HDc + d) * Sc + kbase + r;
            Vs[r * 64 + d] = __half2float(VTH[gv]) + __half2float(VTL[gv]);
        }
        __syncthreads();
        if (tid < 128) {
            int kmax = (kt == qb) ? (row + 1) : 128;
            for (int c = 0; c < kmax; c++) {
                float s = 0.f;
                #pragma unroll
                for (int d = 0; d < HDc; d++) s = fmaf(q[d], Ks[c * 64 + d], s);
                float mn = fmaxf(m, s);
                float cf = fast_exp2(m - mn);
                float p  = fast_exp2(s - mn);
                l = l * cf + p;
                #pragma unroll
                for (int d = 0; d < HDc; d++)
                    o[d] = o[d] * cf + p * Vs[c * 64 + d];
                m = mn;
            }
        }
    }
    if (tid < 128) {
        float inv_l = 1.0f / l;
        #pragma unroll
        for (int d = 0; d < HDc; d++) {
            float v = o[d] * inv_l;
            __half h, lo;
            split_h(v, h, lo);
            size_t go = (((size_t)(b * Sc + qi)) * NHc + hd) * HDc + d;
            ATH[go] = h;
            ATL[go] = lo;
        }
    }
#endif
}

// ---------------------------------------------------------------------------
// launch
// ---------------------------------------------------------------------------
extern "C" void kernel_launch(void* const* d_in, const int* in_sizes, int n_in,
                              void* d_out, int out_size) {
    (void)in_sizes; (void)n_in; (void)out_size;
    const float* x   = (const float*)d_in[0];
    const int*   pos = (const int*)  d_in[1];
    const float* Wq  = (const float*)d_in[2];
    const float* bq  = (const float*)d_in[3];
    const float* Wk  = (const float*)d_in[4];
    const float* bk  = (const float*)d_in[5];
    const float* Wv  = (const float*)d_in[6];
    const float* bv  = (const float*)d_in[7];
    const float* Wo  = (const float*)d_in[8];
    float* out = (float*)d_out;

    float *qkv, *cs, *sn, *bc;
    __half *xh, *xl, *qh, *ql, *kh, *kl, *vth, *vtl, *ath, *atl;
    __half *wch, *wcl, *woh, *wol;
    cudaGetSymbolAddress((void**)&qkv, g_qkv);
    cudaGetSymbolAddress((void**)&cs,  g_cos);
    cudaGetSymbolAddress((void**)&sn,  g_sin);
    cudaGetSymbolAddress((void**)&bc,  g_bc);
    cudaGetSymbolAddress((void**)&xh,  g_xh);
    cudaGetSymbolAddress((void**)&xl,  g_xl);
    cudaGetSymbolAddress((void**)&qh,  g_qh);
    cudaGetSymbolAddress((void**)&ql,  g_ql);
    cudaGetSymbolAddress((void**)&kh,  g_kh);
    cudaGetSymbolAddress((void**)&kl,  g_kl);
    cudaGetSymbolAddress((void**)&vth, g_vth);
    cudaGetSymbolAddress((void**)&vtl, g_vtl);
    cudaGetSymbolAddress((void**)&ath, g_ath);
    cudaGetSymbolAddress((void**)&atl, g_atl);
    cudaGetSymbolAddress((void**)&wch, g_wch);
    cudaGetSymbolAddress((void**)&wcl, g_wcl);
    cudaGetSymbolAddress((void**)&woh, g_woh);
    cudaGetSymbolAddress((void**)&wol, g_wol);

    cudaFuncSetAttribute(tc_gemm, cudaFuncAttributeMaxDynamicSharedMemorySize, SM_GTOTAL);
    cudaFuncSetAttribute(attn_tc, cudaFuncAttributeMaxDynamicSharedMemorySize, AS_TOTAL);

    const float SCALE = 0.125f * 1.4426950408889634f;
    dim3 tb(32, 8);

    // 0) operand prep
    xsplit_kernel<<<(MQ * Hc / 4 + 255) / 256, 256>>>(x, xh, xl, MQ * Hc / 4);
    wconv_kernel<<<dim3(64, 64), tb>>>(Wq, wch,                       wcl,                       2048, 2048);
    wconv_kernel<<<dim3(16, 64), tb>>>(Wk, wch + (size_t)2048 * 2048, wcl + (size_t)2048 * 2048, 2048, 512);
    wconv_kernel<<<dim3(16, 64), tb>>>(Wv, wch + (size_t)2560 * 2048, wcl + (size_t)2560 * 2048, 2048, 512);
    wconv_kernel<<<dim3(64, 64), tb>>>(Wo, woh, wol, 2048, 2048);
    bcat_kernel<<<12, 256>>>(bq, bk, bv, bc);
    cossin_kernel<<<(MQ * HDc + 255) / 256, 256>>>(pos, cs, sn);

    // 1) fused QKV projection (128x256 tiles)
    tc_gemm<<<dim3(NQKV / 256, MQ / 128), GEMM_THREADS, SM_GTOTAL>>>(
        xh, xl, wch, wcl, bc, qkv, NQKV, Hc);

    // 2) RoPE + split; V transpose + split
    rope_split_kernel<<<(MQ * NHc * 32 + 255) / 256, 256>>>(qkv, 0,    cs, sn, qh, ql, NHc,  SCALE, MQ * NHc * 32);
    rope_split_kernel<<<(MQ * NKVc * 32 + 255) / 256, 256>>>(qkv, 2048, cs, sn, kh, kl, NKVc, 1.0f,  MQ * NKVc * 32);
    vtrans_kernel<<<dim3(Sc / 32, HDc / 32, Bc * NKVc), tb>>>(qkv, vth, vtl);

    // 3) tensor-core causal GQA attention (lean 2-CTA/SM, P hi-only PV)
    attn_tc<<<dim3(16, NHc, Bc), ATT_THREADS, AS_TOTAL>>>(qh, ql, kh, kl, vth, vtl, ath, atl);

    // 4) output projection (128x256 tiles)
    tc_gemm<<<dim3(2048 / 256, MQ / 128), GEMM_THREADS, SM_GTOTAL>>>(
        ath, atl, woh, wol, nullptr, out, 2048, Hc);
}

// round 16
// speedup vs baseline: 1.4127x; 1.4127x over previous
#include <cuda_runtime.h>
#include <cuda_fp16.h>
#include <math.h>
#include <stdint.h>

// Problem constants
#define Bc   2
#define Sc   2048
#define Hc   2048
#define NHc  32
#define NKVc 8
#define HDc  64
#define MQ   (Bc * Sc)          // 4096 rows
#define NQKV 3072               // fused QKV output columns (2048 q | 512 k | 512 v)

#if defined(__CUDA_ARCH__) && defined(__CUDA_ARCH_FEAT_SM103_ALL)
#define HAS_TCGEN05 1
#else
#define HAS_TCGEN05 0
#endif

// ---------------------------------------------------------------------------
// Scratch (device globals)
// ---------------------------------------------------------------------------
__device__ float  g_qkv[(size_t)MQ * NQKV];             // fused projection output
__device__ float  g_cos[(size_t)MQ * HDc];
__device__ float  g_sin[(size_t)MQ * HDc];
__device__ float  g_bc [NQKV];                          // fused bias
// fp16 hi/lo split operands
__device__ __half g_xh [(size_t)MQ * Hc],        g_xl [(size_t)MQ * Hc];
__device__ __half g_qh [(size_t)MQ * NHc * HDc], g_ql [(size_t)MQ * NHc * HDc];
__device__ __half g_kh [(size_t)MQ * NKVc * HDc], g_kl [(size_t)MQ * NKVc * HDc];
__device__ __half g_vth[(size_t)Bc * NKVc * HDc * Sc], g_vtl[(size_t)Bc * NKVc * HDc * Sc];
__device__ __half g_ath[(size_t)MQ * Hc],        g_atl[(size_t)MQ * Hc];
// transposed + fp16-split weights: [N, K] row-major
__device__ __half g_wch[(size_t)NQKV * 2048], g_wcl[(size_t)NQKV * 2048];  // fused QKV
__device__ __half g_woh[(size_t)2048 * 2048], g_wol[(size_t)2048 * 2048];

// ---------------------------------------------------------------------------
// helpers
// ---------------------------------------------------------------------------
__device__ __forceinline__ uint32_t smem_u32(const void* p) {
    uint32_t a;
    asm("{ .reg .u64 t; cvta.to.shared.u64 t, %1; cvt.u32.u64 %0, t; }" : "=r"(a) : "l"(p));
    return a;
}
__device__ __forceinline__ float fast_exp2(float x) {
    float y;
    asm("ex2.approx.ftz.f32 %0, %1;" : "=f"(y) : "f"(x));
    return y;
}
__device__ __forceinline__ void split_h(float x, __half& h, __half& l) {
    h = __float2half_rn(x);
    l = __float2half_rn(x - __half2float(h));
}

#if HAS_TCGEN05
__device__ __forceinline__ uint64_t mk_desc(uint32_t addr) {
    // SW128, version=1 (Blackwell), SBO=64, LBO=1
    return ((uint64_t)2 << 61) | ((uint64_t)1 << 46) | ((uint64_t)64 << 32) |
           ((uint64_t)1 << 16) | ((uint64_t)((addr >> 4) & 0x3FFF));
}
__device__ __forceinline__ void mma_f16(uint32_t d, uint64_t ad, uint64_t bd,
                                        uint32_t idesc, uint32_t en) {
    asm volatile(
        "{\n\t.reg .pred p;\n\t"
        "setp.ne.u32 p, %4, 0;\n\t"
        "tcgen05.mma.cta_group::1.kind::f16 [%0], %1, %2, %3, {%5, %5, %5, %5}, p;\n\t}"
        :: "r"(d), "l"(ad), "l"(bd), "r"(idesc), "r"(en), "r"(0u) : "memory");
}
__device__ __forceinline__ void mma_f16_ts(uint32_t d, uint32_t a, uint64_t bd,
                                           uint32_t idesc, uint32_t en) {
    asm volatile(
        "{\n\t.reg .pred p;\n\t"
        "setp.ne.u32 p, %4, 0;\n\t"
        "tcgen05.mma.cta_group::1.kind::f16 [%0], [%1], %2, %3, {%5, %5, %5, %5}, p;\n\t}"
        :: "r"(d), "r"(a), "l"(bd), "r"(idesc), "r"(en), "r"(0u) : "memory");
}
__device__ __forceinline__ void mbar_wait(uint32_t m, uint32_t par) {
    asm volatile(
        "{\n\t.reg .pred P;\n\t"
        "WL%=:\n\t"
        "mbarrier.try_wait.parity.acquire.cta.shared::cta.b64 P, [%0], %1, 0x989680;\n\t"
        "@!P bra WL%=;\n\t}"
        :: "r"(m), "r"(par) : "memory");
}
__device__ __forceinline__ void ldtm32(uint32_t* r, uint32_t addr) {
    asm volatile(
        "tcgen05.ld.sync.aligned.32x32b.x32.b32 "
        "{%0, %1, %2, %3, %4, %5, %6, %7, "
        " %8, %9, %10, %11, %12, %13, %14, %15, "
        " %16, %17, %18, %19, %20, %21, %22, %23, "
        " %24, %25, %26, %27, %28, %29, %30, %31}, [%32];"
        : "=r"(r[0]),  "=r"(r[1]),  "=r"(r[2]),  "=r"(r[3]),
          "=r"(r[4]),  "=r"(r[5]),  "=r"(r[6]),  "=r"(r[7]),
          "=r"(r[8]),  "=r"(r[9]),  "=r"(r[10]), "=r"(r[11]),
          "=r"(r[12]), "=r"(r[13]), "=r"(r[14]), "=r"(r[15]),
          "=r"(r[16]), "=r"(r[17]), "=r"(r[18]), "=r"(r[19]),
          "=r"(r[20]), "=r"(r[21]), "=r"(r[22]), "=r"(r[23]),
          "=r"(r[24]), "=r"(r[25]), "=r"(r[26]), "=r"(r[27]),
          "=r"(r[28]), "=r"(r[29]), "=r"(r[30]), "=r"(r[31])
        : "r"(addr));
}
__device__ __forceinline__ void sttm32(uint32_t addr, const uint32_t* r) {
    asm volatile(
        "tcgen05.st.sync.aligned.32x32b.x32.b32 [%0], "
        "{%1, %2, %3, %4, %5, %6, %7, %8, "
        " %9, %10, %11, %12, %13, %14, %15, %16, "
        " %17, %18, %19, %20, %21, %22, %23, %24, "
        " %25, %26, %27, %28, %29, %30, %31, %32};"
        :: "r"(addr),
           "r"(r[0]),  "r"(r[1]),  "r"(r[2]),  "r"(r[3]),
           "r"(r[4]),  "r"(r[5]),  "r"(r[6]),  "r"(r[7]),
           "r"(r[8]),  "r"(r[9]),  "r"(r[10]), "r"(r[11]),
           "r"(r[12]), "r"(r[13]), "r"(r[14]), "r"(r[15]),
           "r"(r[16]), "r"(r[17]), "r"(r[18]), "r"(r[19]),
           "r"(r[20]), "r"(r[21]), "r"(r[22]), "r"(r[23]),
           "r"(r[24]), "r"(r[25]), "r"(r[26]), "r"(r[27]),
           "r"(r[28]), "r"(r[29]), "r"(r[30]), "r"(r[31])
        : "memory");
}
__device__ __forceinline__ void sttm16(uint32_t addr, const uint32_t* r) {
    asm volatile(
        "tcgen05.st.sync.aligned.32x32b.x16.b32 [%0], "
        "{%1, %2, %3, %4, %5, %6, %7, %8, "
        " %9, %10, %11, %12, %13, %14, %15, %16};"
        :: "r"(addr),
           "r"(r[0]),  "r"(r[1]),  "r"(r[2]),  "r"(r[3]),
           "r"(r[4]),  "r"(r[5]),  "r"(r[6]),  "r"(r[7]),
           "r"(r[8]),  "r"(r[9]),  "r"(r[10]), "r"(r[11]),
           "r"(r[12]), "r"(r[13]), "r"(r[14]), "r"(r[15])
        : "memory");
}
#endif

// ---------------------------------------------------------------------------
// mRoPE cos/sin table
// ---------------------------------------------------------------------------
__global__ void cossin_kernel(const int* __restrict__ pos,
                              float* __restrict__ cosb,
                              float* __restrict__ sinb) {
    int idx = blockIdx.x * blockDim.x + threadIdx.x;
    if (idx >= Bc * Sc * HDc) return;
    int d  = idx & 63;
    int bs = idx >> 6;
    int i  = d & 31;
    int sec = (i < 16) ? 0 : 1;
    float p = (float)pos[sec * (Bc * Sc) + bs];
    float inv_freq = exp2f(-0.6228615177913804f * (float)i);
    float ang = p * inv_freq;
    float s, c;
    sincosf(ang, &s, &c);
    cosb[idx] = c;
    sinb[idx] = s;
}

// ---------------------------------------------------------------------------
// x -> fp16 hi/lo split
// ---------------------------------------------------------------------------
__global__ void xsplit_kernel(const float* __restrict__ X,
                              __half* __restrict__ Xh, __half* __restrict__ Xl,
                              int n4) {
    int idx = blockIdx.x * blockDim.x + threadIdx.x;
    if (idx >= n4) return;
    float4 v = ((const float4*)X)[idx];
    __half h, l;
    split_h(v.x, h, l); Xh[idx*4+0] = h; Xl[idx*4+0] = l;
    split_h(v.y, h, l); Xh[idx*4+1] = h; Xl[idx*4+1] = l;
    split_h(v.z, h, l); Xh[idx*4+2] = h; Xl[idx*4+2] = l;
    split_h(v.w, h, l); Xh[idx*4+3] = h; Xl[idx*4+3] = l;
}

// ---------------------------------------------------------------------------
// bias concat: [bq | bk | bv] -> bc[3072]
// ---------------------------------------------------------------------------
__global__ void bcat_kernel(const float* __restrict__ bq, const float* __restrict__ bk,
                            const float* __restrict__ bv, float* __restrict__ bc) {
    int i = blockIdx.x * 256 + threadIdx.x;
    if (i < 2048)      bc[i] = bq[i];
    else if (i < 2560) bc[i] = bk[i - 2048];
    else if (i < 3072) bc[i] = bv[i - 2560];
}

// ---------------------------------------------------------------------------
// RoPE + fp16 split from fused qkv buffer (row stride NQKV, column offset)
// ---------------------------------------------------------------------------
__global__ void rope_split_kernel(const float* __restrict__ X, int coloff,
                                  const float* __restrict__ cosb,
                                  const float* __restrict__ sinb,
                                  __half* __restrict__ Xh, __half* __restrict__ Xl,
                                  int nheads, float scale, int total_pairs) {
    int idx = blockIdx.x * blockDim.x + threadIdx.x;
    if (idx >= total_pairs) return;
    int d    = idx & 31;
    int rest = idx >> 5;                    // bs*nheads + h
    int bs   = rest / nheads;
    int h    = rest - bs * nheads;
    const float* p  = X + (size_t)bs * NQKV + coloff + h * HDc;
    const float* cb = cosb + (size_t)bs * HDc;
    const float* sb = sinb + (size_t)bs * HDc;
    float x1 = p[d], x2 = p[d + 32];
    float y1 = (x1 * cb[d]      - x2 * sb[d])      * scale;
    float y2 = (x2 * cb[d + 32] + x1 * sb[d + 32]) * scale;
    __half hh, ll;
    split_h(y1, hh, ll);
    Xh[(size_t)rest * HDc + d] = hh;  Xl[(size_t)rest * HDc + d] = ll;
    split_h(y2, hh, ll);
    Xh[(size_t)rest * HDc + d + 32] = hh;  Xl[(size_t)rest * HDc + d + 32] = ll;
}

// ---------------------------------------------------------------------------
// Weight transpose + fp16 hi/lo split: W[K,N] -> Th[N,K], Tl[N,K]
// ---------------------------------------------------------------------------
__global__ void wconv_kernel(const float* __restrict__ W,
                             __half* __restrict__ Th, __half* __restrict__ Tl,
                             int K, int N) {
    __shared__ float t[32][33];
    int n0 = blockIdx.x * 32, k0 = blockIdx.y * 32;
    int c = threadIdx.x, r0 = threadIdx.y;          // block (32,8)
    #pragma unroll
    for (int i = 0; i < 4; i++) {
        int kk = r0 + i * 8;
        t[kk][c] = W[(size_t)(k0 + kk) * N + n0 + c];
    }
    __syncthreads();
    #pragma unroll
    for (int i = 0; i < 4; i++) {
        int nn = r0 + i * 8;
        float v = t[c][nn];
        __half h, l;
        split_h(v, h, l);
        size_t o = (size_t)(n0 + nn) * K + k0 + c;
        Th[o] = h;
        Tl[o] = l;
    }
}

// ---------------------------------------------------------------------------
// V transpose + split from fused qkv: qkv[.., 2560 + kv*64 + d] -> vt[b,kv,d,s]
// ---------------------------------------------------------------------------
__global__ void vtrans_kernel(const float* __restrict__ QKV,
                              __half* __restrict__ VTh, __half* __restrict__ VTl) {
    __shared__ float t[32][33];
    int s0 = blockIdx.x * 32, d0 = blockIdx.y * 32;
    int bkv = blockIdx.z;
    int b = bkv >> 3, kv = bkv & 7;
    int c = threadIdx.x, r0 = threadIdx.y;   // block (32,8)
    #pragma unroll
    for (int i = 0; i < 4; i++) {
        int ss = r0 + i * 8;
        t[ss][c] = QKV[(size_t)(b * Sc + s0 + ss) * NQKV + 2560 + kv * HDc + d0 + c];
    }
    __syncthreads();
    #pragma unroll
    for (int i = 0; i < 4; i++) {
        int dd = r0 + i * 8;
        __half h, l;
        split_h(t[c][dd], h, l);
        size_t o = ((size_t)bkv * HDc + d0 + dd) * Sc + s0 + c;
        VTh[o] = h;
        VTl[o] = l;
    }
}

// ---------------------------------------------------------------------------
// fp16x3 GEMM, 128x256 CTA tile: C = A @ Bt^T   (unchanged from R9)
// ---------------------------------------------------------------------------
#define GEMM_THREADS 256
#define SM_TMEMPTR 0
#define SM_MBAR    16
#define SM_TILES   1024
#define GTILE_A    16384            // 128 rows x 128 bytes (64 fp16)
// buffer layout: Ah @0 | Al @16384 | Bh @32768 | Bl @65536  (96KB)
#define GBUF_B     98304
#define SM_GTOTAL  (SM_TILES + 2 * GBUF_B)   // 197632; epilogue reuses tiles

__global__ __launch_bounds__(GEMM_THREADS, 1)
void tc_gemm(const __half* __restrict__ Ah, const __half* __restrict__ Al,
             const __half* __restrict__ Bh, const __half* __restrict__ Bl,
             const float* __restrict__ bias, float* __restrict__ C,
             int N, int K) {
    extern __shared__ char sm[];
    int tid = threadIdx.x;
    int m0 = blockIdx.y * 128, n0 = blockIdx.x * 256;

#if HAS_TCGEN05
    uint32_t sb = smem_u32(sm);
    if (tid == 0) {
        asm volatile("mbarrier.init.shared.b64 [%0], 1;" :: "r"(sb + SM_MBAR)     : "memory");
        asm volatile("mbarrier.init.shared.b64 [%0], 1;" :: "r"(sb + SM_MBAR + 8) : "memory");
    }
    if (tid < 32) {
        asm volatile("tcgen05.alloc.cta_group::1.sync.aligned.shared::cta.b32 [%0], %1;"
                     :: "r"(sb + SM_TMEMPTR), "r"(256u) : "memory");
        asm volatile("tcgen05.relinquish_alloc_permit.cta_group::1.sync.aligned;");
    }
    __syncthreads();
    uint32_t tmem;
    asm volatile("ld.shared.b32 %0, [%1];" : "=r"(tmem) : "r"(sb + SM_TMEMPTR));

    const uint32_t idesc = (1u << 4) | (32u << 17) | (8u << 24);  // f16, N=256, M=128
    const int NC = K >> 6;                                        // 64-wide K chunks

    auto ldg_tiles = [&](int k0, float4* ra, float4* rb) {
        #pragma unroll
        for (int i2 = 0; i2 < 4; i2++) {           // A: 128 rows
            int idx = tid + i2 * 256;
            int r = idx >> 3, c8 = idx & 7;
            size_t ga = (size_t)(m0 + r) * K + k0 + c8 * 8;
            ra[i2 * 2 + 0] = *(const float4*)(Ah + ga);
            ra[i2 * 2 + 1] = *(const float4*)(Al + ga);
        }
        #pragma unroll
        for (int i2 = 0; i2 < 8; i2++) {           // B: 256 rows
            int idx = tid + i2 * 256;
            int r = idx >> 3, c8 = idx & 7;
            size_t gb = (size_t)(n0 + r) * K + k0 + c8 * 8;
            rb[i2 * 2 + 0] = *(const float4*)(Bh + gb);
            rb[i2 * 2 + 1] = *(const float4*)(Bl + gb);
        }
    };
    auto sts_tiles = [&](int buf, const float4* ra, const float4* rb) {
        char* base = sm + SM_TILES + (size_t)buf * GBUF_B;
        #pragma unroll
        for (int i2 = 0; i2 < 4; i2++) {
            int idx = tid + i2 * 256;
            int r = idx >> 3, c8 = idx & 7;
            uint32_t off = (uint32_t)(r * 128 + c8 * 16);
            off ^= (off >> 3) & 0x70;
            *(float4*)(base + off)           = ra[i2 * 2 + 0];
            *(float4*)(base + GTILE_A + off) = ra[i2 * 2 + 1];
        }
        #pragma unroll
        for (int i2 = 0; i2 < 8; i2++) {
            int idx = tid + i2 * 256;
            int r = idx >> 3, c8 = idx & 7;
            uint32_t off = (uint32_t)(r * 128 + c8 * 16);
            off ^= (off >> 3) & 0x70;
            *(float4*)(base + 32768 + off) = rb[i2 * 2 + 0];
            *(float4*)(base + 65536 + off) = rb[i2 * 2 + 1];
        }
    };

    {   // prologue: chunk 0 straight to smem
        float4 ra[8], rb[16];
        ldg_tiles(0, ra, rb);
        sts_tiles(0, ra, rb);
    }
    int ph0 = 0, ph1 = 0;
    for (int c = 0; c < NC; ++c) {
        int cur = c & 1;
        __syncthreads();   // tiles for chunk c visible
        if (tid == 0) {
            asm volatile("fence.proxy.async.shared::cta;" ::: "memory");
            uint32_t tb = sb + SM_TILES + (uint32_t)cur * GBUF_B;
            uint64_t ahd = mk_desc(tb);
            uint64_t ald = mk_desc(tb + GTILE_A);
            uint64_t bhd = mk_desc(tb + 32768);
            uint64_t bld = mk_desc(tb + 65536);
            #pragma unroll
            for (int ks = 0; ks < 4; ++ks) {           // 16 fp16 per step
                uint32_t en0 = (c == 0 && ks == 0) ? 0u : 1u;
                mma_f16(tmem, ahd + ks * 2, bhd + ks * 2, idesc, en0);
                mma_f16(tmem, ahd + ks * 2, bld + ks * 2, idesc, 1u);
                mma_f16(tmem, ald + ks * 2, bhd + ks * 2, idesc, 1u);
            }
            asm volatile(
                "tcgen05.commit.cta_group::1.mbarrier::arrive::one.shared::cluster.b64 [%0];"
                :: "r"(sb + SM_MBAR + (uint32_t)cur * 8) : "memory");
        }
        if (c + 1 < NC) {
            int nxt = cur ^ 1;
            float4 ra[8], rb[16];
            ldg_tiles((c + 1) << 6, ra, rb);   // LDG overlaps MMA + wait
            if (c >= 1) {
                mbar_wait(sb + SM_MBAR + (uint32_t)nxt * 8, nxt ? ph1 : ph0);
                if (nxt) ph1 ^= 1; else ph0 ^= 1;
            }
            sts_tiles(nxt, ra, rb);
        }
    }
    {
        int last = (NC - 1) & 1;
        mbar_wait(sb + SM_MBAR + (uint32_t)last * 8, last ? ph1 : ph0);
    }
    asm volatile("tcgen05.fence::after_thread_sync;" ::: "memory");
    __syncthreads();

    // epilogue: 8 col-groups of 32 (stage reuses tile smem)
    float* stage = (float*)(sm + SM_TILES);
    int wid = tid >> 5, lid = tid & 31;
    for (int g = 0; g < 8; ++g) {
        if (tid < 128) {
            uint32_t d[32];
            ldtm32(d, tmem + (uint32_t)g * 32);
            asm volatile("tcgen05.wait::ld.sync.aligned;" ::: "memory");
            int row = wid * 32 + lid;
            #pragma unroll
            for (int j = 0; j < 32; ++j)
                stage[row * 33 + j] = __uint_as_float(d[j]);
        }
        __syncthreads();
        #pragma unroll
        for (int i = 0; i < 4; ++i) {
            int rr = (tid >> 3) + i * 32;
            int c4 = tid & 7;
            float x0 = stage[rr * 33 + c4 * 4 + 0];
            float x1 = stage[rr * 33 + c4 * 4 + 1];
            float x2 = stage[rr * 33 + c4 * 4 + 2];
            float x3 = stage[rr * 33 + c4 * 4 + 3];
            int n = n0 + g * 32 + c4 * 4;
            if (bias) {
                x0 += bias[n + 0]; x1 += bias[n + 1];
                x2 += bias[n + 2]; x3 += bias[n + 3];
            }
            *(float4*)(C + (size_t)(m0 + rr) * N + n) = make_float4(x0, x1, x2, x3);
        }
        __syncthreads();
    }

    if (tid < 32) {
        asm volatile("tcgen05.dealloc.cta_group::1.sync.aligned.b32 %0, %1;"
                     :: "r"(tmem), "r"(256u));
    }
#else
    // FFMA fallback (plain sm_103 pass; GB300 loads the sm_103a cubin)
    float (*As)[128] = (float (*)[128])(sm);
    float (*Bs)[128] = (float (*)[128])(sm + 8192);
    int tcol = tid & 15;
    int trow = tid >> 4;
    for (int nh = 0; nh < 2; nh++) {        // two 128-col halves of the 256 tile
        int nb = n0 + nh * 128;
        float acc[8][8];
        #pragma unroll
        for (int i = 0; i < 8; i++)
            #pragma unroll
            for (int j = 0; j < 8; j++) acc[i][j] = 0.f;
        for (int k0 = 0; k0 < K; k0 += 16) {
            for (int idx = tid; idx < 512; idx += 256) {
                int r  = idx >> 2;
                int c4 = idx & 3;
                #pragma unroll
                for (int e = 0; e < 4; e++) {
                    int kk = c4 * 4 + e;
                    size_t ga = (size_t)(m0 + r) * K + k0 + kk;
                    size_t gb = (size_t)(nb + r) * K + k0 + kk;
                    As[kk][r] = __half2float(Ah[ga]) + __half2float(Al[ga]);
                    Bs[kk][r] = __half2float(Bh[gb]) + __half2float(Bl[gb]);
                }
            }
            __syncthreads();
            #pragma unroll
            for (int kk = 0; kk < 16; kk++) {
                float ra[8], rb[8];
                *(float4*)&ra[0] = *(const float4*)&As[kk][trow * 8];
                *(float4*)&ra[4] = *(const float4*)&As[kk][trow * 8 + 4];
                *(float4*)&rb[0] = *(const float4*)&Bs[kk][tcol * 8];
                *(float4*)&rb[4] = *(const float4*)&Bs[kk][tcol * 8 + 4];
                #pragma unroll
                for (int i = 0; i < 8; i++)
                    #pragma unroll
                    for (int j = 0; j < 8; j++)
                        acc[i][j] = fmaf(ra[i], rb[j], acc[i][j]);
            }
            __syncthreads();
        }
        #pragma unroll
        for (int i = 0; i < 8; i++) {
            int m = m0 + trow * 8 + i;
            #pragma unroll
            for (int jj = 0; jj < 8; jj++) {
                int n = nb + tcol * 8 + jj;
                float v = acc[i][jj];
                if (bias) v += bias[n];
                C[(size_t)m * N + n] = v;
            }
        }
        __syncthreads();
    }
#endif
}

// ---------------------------------------------------------------------------
// Tensor-core causal GQA attention (fp16x3), LEAN 2-CTA/SM + split KV tail:
//  K(i+1) stores to smem right after PV(i) issues (K(i) already consumed by
//  QK(i)); V(i+1) LDGs into registers under PV(i); after MPV wait only the
//  V STS is exposed.
//  TMEM: S @0 (128 f32; P overlays after read: Ph @0..63, Pl @64..127) | O @128
// ---------------------------------------------------------------------------
#define ATT_THREADS 128
#define AS_TMEM   0
#define AS_MQK    16
#define AS_MPV    24
#define AS_Q      1024               // Qh 16K | Ql 16K
#define AS_KV     (AS_Q + 32768)     // Kh 16K | Kl 16K | Vh 2x8K | Vl 2x8K
#define AS_TOTAL  (AS_KV + 65536 + 64)   // ~99KB -> 2 CTAs/SM

__global__ __launch_bounds__(ATT_THREADS, 2)
void attn_tc(const __half* __restrict__ QH, const __half* __restrict__ QL,
             const __half* __restrict__ KH, const __half* __restrict__ KL,
             const __half* __restrict__ VTH, const __half* __restrict__ VTL,
             __half* __restrict__ ATH, __half* __restrict__ ATL) {
    extern __shared__ char sm[];
    int tid = threadIdx.x;
    int qb = 15 - (int)blockIdx.x;          // big tiles first
    int hd = blockIdx.y, b = blockIdx.z;
    int khead = hd >> 2;

#if HAS_TCGEN05
    uint32_t sb = smem_u32(sm);
    if (tid == 0) {
        asm volatile("mbarrier.init.shared.b64 [%0], 1;" :: "r"(sb + AS_MQK) : "memory");
        asm volatile("mbarrier.init.shared.b64 [%0], 1;" :: "r"(sb + AS_MPV) : "memory");
    }
    if (tid < 32) {
        asm volatile("tcgen05.alloc.cta_group::1.sync.aligned.shared::cta.b32 [%0], %1;"
                     :: "r"(sb + AS_TMEM), "r"(256u) : "memory");
        asm volatile("tcgen05.relinquish_alloc_permit.cta_group::1.sync.aligned;");
    }
    __syncthreads();
    uint32_t tmem;
    asm volatile("ld.shared.b32 %0, [%1];" : "=r"(tmem) : "r"(sb + AS_TMEM));

    const uint32_t IDQK = (1u << 4) | (16u << 17) | (8u << 24);  // f16 M128 N128
    const uint32_t IDPV = (1u << 4) | (8u  << 17) | (8u << 24);  // f16 M128 N64
    const uint32_t TM_O = 128;

    // ---- Q tile (once): 2048 f4 over 128 threads ----
    #pragma unroll
    for (int i2 = 0; i2 < 8; i2++) {
        int idx = tid + i2 * 128;            // 0..1023
        int r = idx >> 3, c8 = idx & 7;
        uint32_t off = (uint32_t)(r * 128 + c8 * 16);
        off ^= (off >> 3) & 0x70;
        size_t go = (((size_t)(b * Sc + qb * 128 + r)) * NHc + hd) * HDc + c8 * 8;
        *(float4*)(sm + AS_Q + off)         = *(const float4*)(QH + go);
        *(float4*)(sm + AS_Q + 16384 + off) = *(const float4*)(QL + go);
    }

    // K loader: straight to smem (8 f4 pairs per thread)
    auto load_k = [&](int kbase) {
        char* base = sm + AS_KV;
        #pragma unroll
        for (int i2 = 0; i2 < 8; i2++) {             // K: 128 rows x 64 fp16
            int idx = tid + i2 * 128;
            int r = idx >> 3, c8 = idx & 7;
            uint32_t off = (uint32_t)(r * 128 + c8 * 16);
            off ^= (off >> 3) & 0x70;
            size_t go = (((size_t)(b * Sc + kbase + r)) * NKVc + khead) * HDc + c8 * 8;
            *(float4*)(base + off)         = *(const float4*)(KH + go);
            *(float4*)(base + 16384 + off) = *(const float4*)(KL + go);
        }
    };
    // V: register-staged (ldg then sts after the buffer frees)
    auto ldg_v = [&](int kbase, float4* rv) {
        #pragma unroll
        for (int i2 = 0; i2 < 8; i2++) {             // V^T: 64 d-rows x 128 keys
            int idx = tid + i2 * 128;
            int d = idx >> 4, c8 = idx & 15;
            size_t go = ((size_t)(b * NKVc + khead) * HDc + d) * Sc + kbase + c8 * 8;
            rv[i2 * 2 + 0] = *(const float4*)(VTH + go);
            rv[i2 * 2 + 1] = *(const float4*)(VTL + go);
        }
    };
    auto sts_v = [&](const float4* rv) {
        char* base = sm + AS_KV;
        #pragma unroll
        for (int i2 = 0; i2 < 8; i2++) {
            int idx = tid + i2 * 128;
            int d = idx >> 4, c8 = idx & 15;
            int sub = c8 >> 3;
            uint32_t off = (uint32_t)(d * 128 + (c8 & 7) * 16);
            off ^= (off >> 3) & 0x70;
            *(float4*)(base + 32768 + sub * 8192 + off) = rv[i2 * 2 + 0];
            *(float4*)(base + 49152 + sub * 8192 + off) = rv[i2 * 2 + 1];
        }
    };

    // QK for current KV buffer -> S @ tmem, commit MQK
    auto issue_qk = [&]() {
        uint32_t kvb = sb + AS_KV;
        uint64_t qhd = mk_desc(sb + AS_Q);
        uint64_t qld = mk_desc(sb + AS_Q + 16384);
        uint64_t khd = mk_desc(kvb);
        uint64_t kld = mk_desc(kvb + 16384);
        #pragma unroll
        for (int ks = 0; ks < 4; ks++) {
            mma_f16(tmem, qhd + ks * 2, khd + ks * 2, IDQK, ks == 0 ? 0u : 1u);
            mma_f16(tmem, qhd + ks * 2, kld + ks * 2, IDQK, 1u);
            mma_f16(tmem, qld + ks * 2, khd + ks * 2, IDQK, 1u);
        }
        asm volatile(
            "tcgen05.commit.cta_group::1.mbarrier::arrive::one.shared::cluster.b64 [%0];"
            :: "r"(sb + AS_MQK) : "memory");
    };

    {   // prologue: KV(0) fully to smem
        load_k(0);
        float4 rv[16];
        ldg_v(0, rv);
        sts_v(rv);
    }
    __syncthreads();
    if (tid == 0) {
        asm volatile("fence.proxy.async.shared::cta;" ::: "memory");
        issue_qk();
    }

    float m_run = -1e30f, l_run = 0.f;
    uint32_t warp_off = ((uint32_t)(tid >> 5)) << 21;
    int row = tid;

    for (int i = 0; i <= qb; i++) {
        // ---- softmax(i): wait QK(i) ----
        mbar_wait(sb + AS_MQK, i & 1);
        asm volatile("tcgen05.fence::after_thread_sync;" ::: "memory");

        float s[128];
        float mx = m_run;
        #pragma unroll
        for (int ch = 0; ch < 4; ch++) {
            uint32_t r32[32];
            ldtm32(r32, tmem + (uint32_t)ch * 32);
            asm volatile("tcgen05.wait::ld.sync.aligned;" ::: "memory");
            #pragma unroll
            for (int j = 0; j < 32; j++) {
                int key = ch * 32 + j;
                float sv = (i == qb && key > row) ? -1e30f : __uint_as_float(r32[j]);
                s[key] = sv;
                mx = fmaxf(mx, sv);
            }
        }
        float corr = fast_exp2(m_run - mx);
        if (i > 0) {
            bool need = !__all_sync(0xffffffffu, mx == m_run);
            if (need) {
                #pragma unroll
                for (int g = 0; g < 2; g++) {
                    uint32_t o32[32];
                    ldtm32(o32, tmem + TM_O + (uint32_t)g * 32);
                    asm volatile("tcgen05.wait::ld.sync.aligned;" ::: "memory");
                    #pragma unroll
                    for (int j = 0; j < 32; j++)
                        o32[j] = __float_as_uint(__uint_as_float(o32[j]) * corr);
                    sttm32(tmem + TM_O + (uint32_t)g * 32 + warp_off, o32);
                }
            }
        } else {
            corr = 0.f;
        }

        // P = exp2(s - mx); pack fp16 hi/lo pairs; overlay S (already in regs)
        float sum = 0.f;
        #pragma unroll
        for (int ch = 0; ch < 4; ch++) {
            uint32_t phw[16], plw[16];
            #pragma unroll
            for (int j = 0; j < 16; j++) {
                float p0 = fast_exp2(s[ch * 32 + j * 2]     - mx);
                float p1 = fast_exp2(s[ch * 32 + j * 2 + 1] - mx);
                sum += p0 + p1;
                __half h0 = __float2half_rn(p0);
                __half h1 = __float2half_rn(p1);
                float l0 = p0 - __half2float(h0);
                float l1 = p1 - __half2float(h1);
                __half2 hp = __halves2half2(h0, h1);
                __half2 lp = __floats2half2_rn(l0, l1);
                phw[j] = *(uint32_t*)&hp;
                plw[j] = *(uint32_t*)&lp;
            }
            sttm16(tmem + (uint32_t)ch * 16 + warp_off, phw);        // Ph @0..63
            sttm16(tmem + 64 + (uint32_t)ch * 16 + warp_off, plw);   // Pl @64..127
        }
        asm volatile("tcgen05.wait::st.sync.aligned;" ::: "memory");
        asm volatile("tcgen05.fence::before_thread_sync;" ::: "memory");

        l_run = l_run * corr + sum;
        m_run = mx;
        __syncthreads();   // all warps' P written

        // ---- PV(i) ----
        if (tid == 0) {
            asm volatile("tcgen05.fence::after_thread_sync;" ::: "memory");
            uint32_t kvb = sb + AS_KV;
            #pragma unroll
            for (int kk = 0; kk < 8; kk++) {             // 16 keys per step
                int sub = kk >> 2, ks = kk & 3;
                uint64_t vh = mk_desc(kvb + 32768 + (uint32_t)sub * 8192) + ks * 2;
                uint64_t vl = mk_desc(kvb + 49152 + (uint32_t)sub * 8192) + ks * 2;
                uint32_t ah = tmem + (uint32_t)kk * 8;
                uint32_t al = tmem + 64 + (uint32_t)kk * 8;
                mma_f16_ts(tmem + TM_O, ah, vh, IDPV, (i == 0 && kk == 0) ? 0u : 1u);
                mma_f16_ts(tmem + TM_O, ah, vl, IDPV, 1u);
                mma_f16_ts(tmem + TM_O, al, vh, IDPV, 1u);
            }
            asm volatile(
                "tcgen05.commit.cta_group::1.mbarrier::arrive::one.shared::cluster.b64 [%0];"
                :: "r"(sb + AS_MPV) : "memory");
        }

        if (i + 1 <= qb) {
            // K(i+1) direct to smem: K(i) was consumed by QK(i) (completed
            // before softmax); overlaps PV(i) on the tensor pipe.
            load_k((i + 1) * 128);
            // V(i+1) into registers: LDG latency overlaps PV(i).
            float4 rv[16];
            ldg_v((i + 1) * 128, rv);
            mbar_wait(sb + AS_MPV, i & 1);   // V(i) consumed by PV(i)
            sts_v(rv);
            __syncthreads();
            if (tid == 0) {
                asm volatile("fence.proxy.async.shared::cta;" ::: "memory");
                issue_qk();
            }
        } else {
            mbar_wait(sb + AS_MPV, i & 1);
        }
    }

    // ---- epilogue: O/l -> fp16 hi/lo att (PV(qb) already waited) ----
    asm volatile("tcgen05.fence::after_thread_sync;" ::: "memory");
    {
        float inv_l = 1.0f / l_run;
        size_t obase = ((size_t)(b * Sc + qb * 128 + row)) * (NHc * HDc) + (size_t)hd * HDc;
        #pragma unroll
        for (int g = 0; g < 2; g++) {
            uint32_t o32[32];
            ldtm32(o32, tmem + TM_O + (uint32_t)g * 32);
            asm volatile("tcgen05.wait::ld.sync.aligned;" ::: "memory");
            #pragma unroll
            for (int j = 0; j < 32; j += 2) {
                float v0 = __uint_as_float(o32[j])     * inv_l;
                float v1 = __uint_as_float(o32[j + 1]) * inv_l;
                __half h0, l0, h1, l1;
                split_h(v0, h0, l0);
                split_h(v1, h1, l1);
                *(__half2*)(ATH + obase + g * 32 + j) = __halves2half2(h0, h1);
                *(__half2*)(ATL + obase + g * 32 + j) = __halves2half2(l0, l1);
            }
        }
    }
    __syncthreads();
    if (tid < 32) {
        asm volatile("tcgen05.dealloc.cta_group::1.sync.aligned.b32 %0, %1;"
                     :: "r"(tmem), "r"(256u));
    }
#else
    // fp32 flash fallback (plain sm_103 pass only)
    float* Ks = (float*)(sm);
    float* Vs = (float*)(sm + 128 * 64 * 4);
    int row = tid & 127;
    int qi = qb * 128 + row;
    float q[HDc], o[HDc];
    float m = -1e30f, l = 0.f;
    if (tid < 128) {
        #pragma unroll
        for (int d = 0; d < HDc; d++) {
            size_t go = (((size_t)(b * Sc + qi)) * NHc + hd) * HDc + d;
            q[d] = __half2float(QH[go]) + __half2float(QL[go]);
            o[d] = 0.f;
        }
    }
    for (int kt = 0; kt <= qb; kt++) {
        int kbase = kt * 128;
        __syncthreads();
        for (int idx = tid; idx < 128 * 64; idx += ATT_THREADS) {
            int r = idx >> 6, d = idx & 63;
            size_t go = (((size_t)(b * Sc + kbase + r)) * NKVc + khead) * HDc + d;
            Ks[r * 64 + d] = __half2float(KH[go]) + __half2float(KL[go]);
            size_t gv = ((size_t)(b * NKVc + khead) * HDc + d) * Sc + kbase + r;
            Vs[r * 64 + d] = __half2float(VTH[gv]) + __half2float(VTL[gv]);
        }
        __syncthreads();
        if (tid < 128) {
            int kmax = (kt == qb) ? (row + 1) : 128;
            for (int c = 0; c < kmax; c++) {
                float s = 0.f;
                #pragma unroll
                for (int d = 0; d < HDc; d++) s = fmaf(q[d], Ks[c * 64 + d], s);
                float mn = fmaxf(m, s);
                float cf = fast_exp2(m - mn);
                float p  = fast_exp2(s - mn);
                l = l * cf + p;
                #pragma unroll
                for (int d = 0; d < HDc; d++)
                    o[d] = o[d] * cf + p * Vs[c * 64 + d];
                m = mn;
            }
        }
    }
    if (tid < 128) {
        float inv_l = 1.0f / l;
        #pragma unroll
        for (int d = 0; d < HDc; d++) {
            float v = o[d] * inv_l;
            __half h, lo;
            split_h(v, h, lo);
            size_t go = (((size_t)(b * Sc + qi)) * NHc + hd) * HDc + d;
            ATH[go] = h;
            ATL[go] = lo;
        }
    }
#endif
}

// ---------------------------------------------------------------------------
// launch
// ---------------------------------------------------------------------------
extern "C" void kernel_launch(void* const* d_in, const int* in_sizes, int n_in,
                              void* d_out, int out_size) {
    (void)in_sizes; (void)n_in; (void)out_size;
    const float* x   = (const float*)d_in[0];
    const int*   pos = (const int*)  d_in[1];
    const float* Wq  = (const float*)d_in[2];
    const float* bq  = (const float*)d_in[3];
    const float* Wk  = (const float*)d_in[4];
    const float* bk  = (const float*)d_in[5];
    const float* Wv  = (const float*)d_in[6];
    const float* bv  = (const float*)d_in[7];
    const float* Wo  = (const float*)d_in[8];
    float* out = (float*)d_out;

    float *qkv, *cs, *sn, *bc;
    __half *xh, *xl, *qh, *ql, *kh, *kl, *vth, *vtl, *ath, *atl;
    __half *wch, *wcl, *woh, *wol;
    cudaGetSymbolAddress((void**)&qkv, g_qkv);
    cudaGetSymbolAddress((void**)&cs,  g_cos);
    cudaGetSymbolAddress((void**)&sn,  g_sin);
    cudaGetSymbolAddress((void**)&bc,  g_bc);
    cudaGetSymbolAddress((void**)&xh,  g_xh);
    cudaGetSymbolAddress((void**)&xl,  g_xl);
    cudaGetSymbolAddress((void**)&qh,  g_qh);
    cudaGetSymbolAddress((void**)&ql,  g_ql);
    cudaGetSymbolAddress((void**)&kh,  g_kh);
    cudaGetSymbolAddress((void**)&kl,  g_kl);
    cudaGetSymbolAddress((void**)&vth, g_vth);
    cudaGetSymbolAddress((void**)&vtl, g_vtl);
    cudaGetSymbolAddress((void**)&ath, g_ath);
    cudaGetSymbolAddress((void**)&atl, g_atl);
    cudaGetSymbolAddress((void**)&wch, g_wch);
    cudaGetSymbolAddress((void**)&wcl, g_wcl);
    cudaGetSymbolAddress((void**)&woh, g_woh);
    cudaGetSymbolAddress((void**)&wol, g_wol);

    cudaFuncSetAttribute(tc_gemm, cudaFuncAttributeMaxDynamicSharedMemorySize, SM_GTOTAL);
    cudaFuncSetAttribute(attn_tc, cudaFuncAttributeMaxDynamicSharedMemorySize, AS_TOTAL);

    const float SCALE = 0.125f * 1.4426950408889634f;
    dim3 tb(32, 8);

    // 0) operand prep
    xsplit_kernel<<<(MQ * Hc / 4 + 255) / 256, 256>>>(x, xh, xl, MQ * Hc / 4);
    wconv_kernel<<<dim3(64, 64), tb>>>(Wq, wch,                       wcl,                       2048, 2048);
    wconv_kernel<<<dim3(16, 64), tb>>>(Wk, wch + (size_t)2048 * 2048, wcl + (size_t)2048 * 2048, 2048, 512);
    wconv_kernel<<<dim3(16, 64), tb>>>(Wv, wch + (size_t)2560 * 2048, wcl + (size_t)2560 * 2048, 2048, 512);
    wconv_kernel<<<dim3(64, 64), tb>>>(Wo, woh, wol, 2048, 2048);
    bcat_kernel<<<12, 256>>>(bq, bk, bv, bc);
    cossin_kernel<<<(MQ * HDc + 255) / 256, 256>>>(pos, cs, sn);

    // 1) fused QKV projection (128x256 tiles)
    tc_gemm<<<dim3(NQKV / 256, MQ / 128), GEMM_THREADS, SM_GTOTAL>>>(
        xh, xl, wch, wcl, bc, qkv, NQKV, Hc);

    // 2) RoPE + split; V transpose + split
    rope_split_kernel<<<(MQ * NHc * 32 + 255) / 256, 256>>>(qkv, 0,    cs, sn, qh, ql, NHc,  SCALE, MQ * NHc * 32);
    rope_split_kernel<<<(MQ * NKVc * 32 + 255) / 256, 256>>>(qkv, 2048, cs, sn, kh, kl, NKVc, 1.0f,  MQ * NKVc * 32);
    vtrans_kernel<<<dim3(Sc / 32, HDc / 32, Bc * NKVc), tb>>>(qkv, vth, vtl);

    // 3) tensor-core causal GQA attention (lean 2-CTA/SM, split KV tail)
    attn_tc<<<dim3(16, NHc, Bc), ATT_THREADS, AS_TOTAL>>>(qh, ql, kh, kl, vth, vtl, ath, atl);

    // 4) output projection (128x256 tiles)
    tc_gemm<<<dim3(2048 / 256, MQ / 128), GEMM_THREADS, SM_GTOTAL>>>(
        ath, atl, woh, wol, nullptr, out, 2048, Hc);
}

// round 17
// speedup vs baseline: 1.4425x; 1.0211x over previous
#include <cuda_runtime.h>
#include <cuda_fp16.h>
#include <math.h>
#include <stdint.h>

// Problem constants
#define Bc   2
#define Sc   2048
#define Hc   2048
#define NHc  32
#define NKVc 8
#define HDc  64
#define MQ   (Bc * Sc)          // 4096 rows
#define NQKV 3072               // fused QKV output columns (2048 q | 512 k | 512 v)

#if defined(__CUDA_ARCH__) && defined(__CUDA_ARCH_FEAT_SM103_ALL)
#define HAS_TCGEN05 1
#else
#define HAS_TCGEN05 0
#endif

// ---------------------------------------------------------------------------
// Scratch (device globals)
// ---------------------------------------------------------------------------
__device__ float  g_qkv[(size_t)MQ * NQKV];             // fused projection output
__device__ float  g_cos[(size_t)MQ * HDc];
__device__ float  g_sin[(size_t)MQ * HDc];
__device__ float  g_bc [NQKV];                          // fused bias
// fp16 hi/lo split operands
__device__ __half g_xh [(size_t)MQ * Hc],        g_xl [(size_t)MQ * Hc];
__device__ __half g_qh [(size_t)MQ * NHc * HDc], g_ql [(size_t)MQ * NHc * HDc];
__device__ __half g_kh [(size_t)MQ * NKVc * HDc], g_kl [(size_t)MQ * NKVc * HDc];
__device__ __half g_vth[(size_t)Bc * NKVc * HDc * Sc], g_vtl[(size_t)Bc * NKVc * HDc * Sc];
__device__ __half g_ath[(size_t)MQ * Hc],        g_atl[(size_t)MQ * Hc];
// transposed + fp16-split weights: [N, K] row-major
__device__ __half g_wch[(size_t)NQKV * 2048], g_wcl[(size_t)NQKV * 2048];  // fused QKV
__device__ __half g_woh[(size_t)2048 * 2048], g_wol[(size_t)2048 * 2048];

// ---------------------------------------------------------------------------
// helpers
// ---------------------------------------------------------------------------
__device__ __forceinline__ uint32_t smem_u32(const void* p) {
    uint32_t a;
    asm("{ .reg .u64 t; cvta.to.shared.u64 t, %1; cvt.u32.u64 %0, t; }" : "=r"(a) : "l"(p));
    return a;
}
__device__ __forceinline__ float fast_exp2(float x) {
    float y;
    asm("ex2.approx.ftz.f32 %0, %1;" : "=f"(y) : "f"(x));
    return y;
}
__device__ __forceinline__ void split_h(float x, __half& h, __half& l) {
    h = __float2half_rn(x);
    l = __float2half_rn(x - __half2float(h));
}

#if HAS_TCGEN05
__device__ __forceinline__ uint64_t mk_desc(uint32_t addr) {
    // SW128, version=1 (Blackwell), SBO=64, LBO=1
    return ((uint64_t)2 << 61) | ((uint64_t)1 << 46) | ((uint64_t)64 << 32) |
           ((uint64_t)1 << 16) | ((uint64_t)((addr >> 4) & 0x3FFF));
}
__device__ __forceinline__ void mma_f16(uint32_t d, uint64_t ad, uint64_t bd,
                                        uint32_t idesc, uint32_t en) {
    asm volatile(
        "{\n\t.reg .pred p;\n\t"
        "setp.ne.u32 p, %4, 0;\n\t"
        "tcgen05.mma.cta_group::1.kind::f16 [%0], %1, %2, %3, {%5, %5, %5, %5}, p;\n\t}"
        :: "r"(d), "l"(ad), "l"(bd), "r"(idesc), "r"(en), "r"(0u) : "memory");
}
__device__ __forceinline__ void mma_f16_ts(uint32_t d, uint32_t a, uint64_t bd,
                                           uint32_t idesc, uint32_t en) {
    asm volatile(
        "{\n\t.reg .pred p;\n\t"
        "setp.ne.u32 p, %4, 0;\n\t"
        "tcgen05.mma.cta_group::1.kind::f16 [%0], [%1], %2, %3, {%5, %5, %5, %5}, p;\n\t}"
        :: "r"(d), "r"(a), "l"(bd), "r"(idesc), "r"(en), "r"(0u) : "memory");
}
__device__ __forceinline__ void mbar_wait(uint32_t m, uint32_t par) {
    asm volatile(
        "{\n\t.reg .pred P;\n\t"
        "WL%=:\n\t"
        "mbarrier.try_wait.parity.acquire.cta.shared::cta.b64 P, [%0], %1, 0x989680;\n\t"
        "@!P bra WL%=;\n\t}"
        :: "r"(m), "r"(par) : "memory");
}
__device__ __forceinline__ void ldtm32(uint32_t* r, uint32_t addr) {
    asm volatile(
        "tcgen05.ld.sync.aligned.32x32b.x32.b32 "
        "{%0, %1, %2, %3, %4, %5, %6, %7, "
        " %8, %9, %10, %11, %12, %13, %14, %15, "
        " %16, %17, %18, %19, %20, %21, %22, %23, "
        " %24, %25, %26, %27, %28, %29, %30, %31}, [%32];"
        : "=r"(r[0]),  "=r"(r[1]),  "=r"(r[2]),  "=r"(r[3]),
          "=r"(r[4]),  "=r"(r[5]),  "=r"(r[6]),  "=r"(r[7]),
          "=r"(r[8]),  "=r"(r[9]),  "=r"(r[10]), "=r"(r[11]),
          "=r"(r[12]), "=r"(r[13]), "=r"(r[14]), "=r"(r[15]),
          "=r"(r[16]), "=r"(r[17]), "=r"(r[18]), "=r"(r[19]),
          "=r"(r[20]), "=r"(r[21]), "=r"(r[22]), "=r"(r[23]),
          "=r"(r[24]), "=r"(r[25]), "=r"(r[26]), "=r"(r[27]),
          "=r"(r[28]), "=r"(r[29]), "=r"(r[30]), "=r"(r[31])
        : "r"(addr));
}
__device__ __forceinline__ void sttm32(uint32_t addr, const uint32_t* r) {
    asm volatile(
        "tcgen05.st.sync.aligned.32x32b.x32.b32 [%0], "
        "{%1, %2, %3, %4, %5, %6, %7, %8, "
        " %9, %10, %11, %12, %13, %14, %15, %16, "
        " %17, %18, %19, %20, %21, %22, %23, %24, "
        " %25, %26, %27, %28, %29, %30, %31, %32};"
        :: "r"(addr),
           "r"(r[0]),  "r"(r[1]),  "r"(r[2]),  "r"(r[3]),
           "r"(r[4]),  "r"(r[5]),  "r"(r[6]),  "r"(r[7]),
           "r"(r[8]),  "r"(r[9]),  "r"(r[10]), "r"(r[11]),
           "r"(r[12]), "r"(r[13]), "r"(r[14]), "r"(r[15]),
           "r"(r[16]), "r"(r[17]), "r"(r[18]), "r"(r[19]),
           "r"(r[20]), "r"(r[21]), "r"(r[22]), "r"(r[23]),
           "r"(r[24]), "r"(r[25]), "r"(r[26]), "r"(r[27]),
           "r"(r[28]), "r"(r[29]), "r"(r[30]), "r"(r[31])
        : "memory");
}
__device__ __forceinline__ void sttm16(uint32_t addr, const uint32_t* r) {
    asm volatile(
        "tcgen05.st.sync.aligned.32x32b.x16.b32 [%0], "
        "{%1, %2, %3, %4, %5, %6, %7, %8, "
        " %9, %10, %11, %12, %13, %14, %15, %16};"
        :: "r"(addr),
           "r"(r[0]),  "r"(r[1]),  "r"(r[2]),  "r"(r[3]),
           "r"(r[4]),  "r"(r[5]),  "r"(r[6]),  "r"(r[7]),
           "r"(r[8]),  "r"(r[9]),  "r"(r[10]), "r"(r[11]),
           "r"(r[12]), "r"(r[13]), "r"(r[14]), "r"(r[15])
        : "memory");
}
#endif

// ---------------------------------------------------------------------------
// mRoPE cos/sin table
// ---------------------------------------------------------------------------
__global__ void cossin_kernel(const int* __restrict__ pos,
                              float* __restrict__ cosb,
                              float* __restrict__ sinb) {
    int idx = blockIdx.x * blockDim.x + threadIdx.x;
    if (idx >= Bc * Sc * HDc) return;
    int d  = idx & 63;
    int bs = idx >> 6;
    int i  = d & 31;
    int sec = (i < 16) ? 0 : 1;
    float p = (float)pos[sec * (Bc * Sc) + bs];
    float inv_freq = exp2f(-0.6228615177913804f * (float)i);
    float ang = p * inv_freq;
    float s, c;
    sincosf(ang, &s, &c);
    cosb[idx] = c;
    sinb[idx] = s;
}

// ---------------------------------------------------------------------------
// x -> fp16 hi/lo split
// ---------------------------------------------------------------------------
__global__ void xsplit_kernel(const float* __restrict__ X,
                              __half* __restrict__ Xh, __half* __restrict__ Xl,
                              int n4) {
    int idx = blockIdx.x * blockDim.x + threadIdx.x;
    if (idx >= n4) return;
    float4 v = ((const float4*)X)[idx];
    __half h, l;
    split_h(v.x, h, l); Xh[idx*4+0] = h; Xl[idx*4+0] = l;
    split_h(v.y, h, l); Xh[idx*4+1] = h; Xl[idx*4+1] = l;
    split_h(v.z, h, l); Xh[idx*4+2] = h; Xl[idx*4+2] = l;
    split_h(v.w, h, l); Xh[idx*4+3] = h; Xl[idx*4+3] = l;
}

// ---------------------------------------------------------------------------
// bias concat: [bq | bk | bv] -> bc[3072]
// ---------------------------------------------------------------------------
__global__ void bcat_kernel(const float* __restrict__ bq, const float* __restrict__ bk,
                            const float* __restrict__ bv, float* __restrict__ bc) {
    int i = blockIdx.x * 256 + threadIdx.x;
    if (i < 2048)      bc[i] = bq[i];
    else if (i < 2560) bc[i] = bk[i - 2048];
    else if (i < 3072) bc[i] = bv[i - 2560];
}

// ---------------------------------------------------------------------------
// RoPE + fp16 split from fused qkv buffer (row stride NQKV, column offset)
// ---------------------------------------------------------------------------
__global__ void rope_split_kernel(const float* __restrict__ X, int coloff,
                                  const float* __restrict__ cosb,
                                  const float* __restrict__ sinb,
                                  __half* __restrict__ Xh, __half* __restrict__ Xl,
                                  int nheads, float scale, int total_pairs) {
    int idx = blockIdx.x * blockDim.x + threadIdx.x;
    if (idx >= total_pairs) return;
    int d    = idx & 31;
    int rest = idx >> 5;                    // bs*nheads + h
    int bs   = rest / nheads;
    int h    = rest - bs * nheads;
    const float* p  = X + (size_t)bs * NQKV + coloff + h * HDc;
    const float* cb = cosb + (size_t)bs * HDc;
    const float* sb = sinb + (size_t)bs * HDc;
    float x1 = p[d], x2 = p[d + 32];
    float y1 = (x1 * cb[d]      - x2 * sb[d])      * scale;
    float y2 = (x2 * cb[d + 32] + x1 * sb[d + 32]) * scale;
    __half hh, ll;
    split_h(y1, hh, ll);
    Xh[(size_t)rest * HDc + d] = hh;  Xl[(size_t)rest * HDc + d] = ll;
    split_h(y2, hh, ll);
    Xh[(size_t)rest * HDc + d + 32] = hh;  Xl[(size_t)rest * HDc + d + 32] = ll;
}

// ---------------------------------------------------------------------------
// Weight transpose + fp16 hi/lo split: W[K,N] -> Th[N,K], Tl[N,K]
// ---------------------------------------------------------------------------
__global__ void wconv_kernel(const float* __restrict__ W,
                             __half* __restrict__ Th, __half* __restrict__ Tl,
                             int K, int N) {
    __shared__ float t[32][33];
    int n0 = blockIdx.x * 32, k0 = blockIdx.y * 32;
    int c = threadIdx.x, r0 = threadIdx.y;          // block (32,8)
    #pragma unroll
    for (int i = 0; i < 4; i++) {
        int kk = r0 + i * 8;
        t[kk][c] = W[(size_t)(k0 + kk) * N + n0 + c];
    }
    __syncthreads();
    #pragma unroll
    for (int i = 0; i < 4; i++) {
        int nn = r0 + i * 8;
        float v = t[c][nn];
        __half h, l;
        split_h(v, h, l);
        size_t o = (size_t)(n0 + nn) * K + k0 + c;
        Th[o] = h;
        Tl[o] = l;
    }
}

// ---------------------------------------------------------------------------
// V transpose + split from fused qkv: qkv[.., 2560 + kv*64 + d] -> vt[b,kv,d,s]
// ---------------------------------------------------------------------------
__global__ void vtrans_kernel(const float* __restrict__ QKV,
                              __half* __restrict__ VTh, __half* __restrict__ VTl) {
    __shared__ float t[32][33];
    int s0 = blockIdx.x * 32, d0 = blockIdx.y * 32;
    int bkv = blockIdx.z;
    int b = bkv >> 3, kv = bkv & 7;
    int c = threadIdx.x, r0 = threadIdx.y;   // block (32,8)
    #pragma unroll
    for (int i = 0; i < 4; i++) {
        int ss = r0 + i * 8;
        t[ss][c] = QKV[(size_t)(b * Sc + s0 + ss) * NQKV + 2560 + kv * HDc + d0 + c];
    }
    __syncthreads();
    #pragma unroll
    for (int i = 0; i < 4; i++) {
        int dd = r0 + i * 8;
        __half h, l;
        split_h(t[c][dd], h, l);
        size_t o = ((size_t)bkv * HDc + d0 + dd) * Sc + s0 + c;
        VTh[o] = h;
        VTl[o] = l;
    }
}

// ---------------------------------------------------------------------------
// fp16x3 GEMM, 128x256 CTA tile: C = A @ Bt^T   (unchanged from R9)
// ---------------------------------------------------------------------------
#define GEMM_THREADS 256
#define SM_TMEMPTR 0
#define SM_MBAR    16
#define SM_TILES   1024
#define GTILE_A    16384            // 128 rows x 128 bytes (64 fp16)
// buffer layout: Ah @0 | Al @16384 | Bh @32768 | Bl @65536  (96KB)
#define GBUF_B     98304
#define SM_GTOTAL  (SM_TILES + 2 * GBUF_B)   // 197632; epilogue reuses tiles

__global__ __launch_bounds__(GEMM_THREADS, 1)
void tc_gemm(const __half* __restrict__ Ah, const __half* __restrict__ Al,
             const __half* __restrict__ Bh, const __half* __restrict__ Bl,
             const float* __restrict__ bias, float* __restrict__ C,
             int N, int K) {
    extern __shared__ char sm[];
    int tid = threadIdx.x;
    int m0 = blockIdx.y * 128, n0 = blockIdx.x * 256;

#if HAS_TCGEN05
    uint32_t sb = smem_u32(sm);
    if (tid == 0) {
        asm volatile("mbarrier.init.shared.b64 [%0], 1;" :: "r"(sb + SM_MBAR)     : "memory");
        asm volatile("mbarrier.init.shared.b64 [%0], 1;" :: "r"(sb + SM_MBAR + 8) : "memory");
    }
    if (tid < 32) {
        asm volatile("tcgen05.alloc.cta_group::1.sync.aligned.shared::cta.b32 [%0], %1;"
                     :: "r"(sb + SM_TMEMPTR), "r"(256u) : "memory");
        asm volatile("tcgen05.relinquish_alloc_permit.cta_group::1.sync.aligned;");
    }
    __syncthreads();
    uint32_t tmem;
    asm volatile("ld.shared.b32 %0, [%1];" : "=r"(tmem) : "r"(sb + SM_TMEMPTR));

    const uint32_t idesc = (1u << 4) | (32u << 17) | (8u << 24);  // f16, N=256, M=128
    const int NC = K >> 6;                                        // 64-wide K chunks

    auto ldg_tiles = [&](int k0, float4* ra, float4* rb) {
        #pragma unroll
        for (int i2 = 0; i2 < 4; i2++) {           // A: 128 rows
            int idx = tid + i2 * 256;
            int r = idx >> 3, c8 = idx & 7;
            size_t ga = (size_t)(m0 + r) * K + k0 + c8 * 8;
            ra[i2 * 2 + 0] = *(const float4*)(Ah + ga);
            ra[i2 * 2 + 1] = *(const float4*)(Al + ga);
        }
        #pragma unroll
        for (int i2 = 0; i2 < 8; i2++) {           // B: 256 rows
            int idx = tid + i2 * 256;
            int r = idx >> 3, c8 = idx & 7;
            size_t gb = (size_t)(n0 + r) * K + k0 + c8 * 8;
            rb[i2 * 2 + 0] = *(const float4*)(Bh + gb);
            rb[i2 * 2 + 1] = *(const float4*)(Bl + gb);
        }
    };
    auto sts_tiles = [&](int buf, const float4* ra, const float4* rb) {
        char* base = sm + SM_TILES + (size_t)buf * GBUF_B;
        #pragma unroll
        for (int i2 = 0; i2 < 4; i2++) {
            int idx = tid + i2 * 256;
            int r = idx >> 3, c8 = idx & 7;
            uint32_t off = (uint32_t)(r * 128 + c8 * 16);
            off ^= (off >> 3) & 0x70;
            *(float4*)(base + off)           = ra[i2 * 2 + 0];
            *(float4*)(base + GTILE_A + off) = ra[i2 * 2 + 1];
        }
        #pragma unroll
        for (int i2 = 0; i2 < 8; i2++) {
            int idx = tid + i2 * 256;
            int r = idx >> 3, c8 = idx & 7;
            uint32_t off = (uint32_t)(r * 128 + c8 * 16);
            off ^= (off >> 3) & 0x70;
            *(float4*)(base + 32768 + off) = rb[i2 * 2 + 0];
            *(float4*)(base + 65536 + off) = rb[i2 * 2 + 1];
        }
    };

    {   // prologue: chunk 0 straight to smem
        float4 ra[8], rb[16];
        ldg_tiles(0, ra, rb);
        sts_tiles(0, ra, rb);
    }
    int ph0 = 0, ph1 = 0;
    for (int c = 0; c < NC; ++c) {
        int cur = c & 1;
        __syncthreads();   // tiles for chunk c visible
        if (tid == 0) {
            asm volatile("fence.proxy.async.shared::cta;" ::: "memory");
            uint32_t tb = sb + SM_TILES + (uint32_t)cur * GBUF_B;
            uint64_t ahd = mk_desc(tb);
            uint64_t ald = mk_desc(tb + GTILE_A);
            uint64_t bhd = mk_desc(tb + 32768);
            uint64_t bld = mk_desc(tb + 65536);
            #pragma unroll
            for (int ks = 0; ks < 4; ++ks) {           // 16 fp16 per step
                uint32_t en0 = (c == 0 && ks == 0) ? 0u : 1u;
                mma_f16(tmem, ahd + ks * 2, bhd + ks * 2, idesc, en0);
                mma_f16(tmem, ahd + ks * 2, bld + ks * 2, idesc, 1u);
                mma_f16(tmem, ald + ks * 2, bhd + ks * 2, idesc, 1u);
            }
            asm volatile(
                "tcgen05.commit.cta_group::1.mbarrier::arrive::one.shared::cluster.b64 [%0];"
                :: "r"(sb + SM_MBAR + (uint32_t)cur * 8) : "memory");
        }
        if (c + 1 < NC) {
            int nxt = cur ^ 1;
            float4 ra[8], rb[16];
            ldg_tiles((c + 1) << 6, ra, rb);   // LDG overlaps MMA + wait
            if (c >= 1) {
                mbar_wait(sb + SM_MBAR + (uint32_t)nxt * 8, nxt ? ph1 : ph0);
                if (nxt) ph1 ^= 1; else ph0 ^= 1;
            }
            sts_tiles(nxt, ra, rb);
        }
    }
    {
        int last = (NC - 1) & 1;
        mbar_wait(sb + SM_MBAR + (uint32_t)last * 8, last ? ph1 : ph0);
    }
    asm volatile("tcgen05.fence::after_thread_sync;" ::: "memory");
    __syncthreads();

    // epilogue: 8 col-groups of 32 (stage reuses tile smem)
    float* stage = (float*)(sm + SM_TILES);
    int wid = tid >> 5, lid = tid & 31;
    for (int g = 0; g < 8; ++g) {
        if (tid < 128) {
            uint32_t d[32];
            ldtm32(d, tmem + (uint32_t)g * 32);
            asm volatile("tcgen05.wait::ld.sync.aligned;" ::: "memory");
            int row = wid * 32 + lid;
            #pragma unroll
            for (int j = 0; j < 32; ++j)
                stage[row * 33 + j] = __uint_as_float(d[j]);
        }
        __syncthreads();
        #pragma unroll
        for (int i = 0; i < 4; ++i) {
            int rr = (tid >> 3) + i * 32;
            int c4 = tid & 7;
            float x0 = stage[rr * 33 + c4 * 4 + 0];
            float x1 = stage[rr * 33 + c4 * 4 + 1];
            float x2 = stage[rr * 33 + c4 * 4 + 2];
            float x3 = stage[rr * 33 + c4 * 4 + 3];
            int n = n0 + g * 32 + c4 * 4;
            if (bias) {
                x0 += bias[n + 0]; x1 += bias[n + 1];
                x2 += bias[n + 2]; x3 += bias[n + 3];
            }
            *(float4*)(C + (size_t)(m0 + rr) * N + n) = make_float4(x0, x1, x2, x3);
        }
        __syncthreads();
    }

    if (tid < 32) {
        asm volatile("tcgen05.dealloc.cta_group::1.sync.aligned.b32 %0, %1;"
                     :: "r"(tmem), "r"(256u));
    }
#else
    // FFMA fallback (plain sm_103 pass; GB300 loads the sm_103a cubin)
    float (*As)[128] = (float (*)[128])(sm);
    float (*Bs)[128] = (float (*)[128])(sm + 8192);
    int tcol = tid & 15;
    int trow = tid >> 4;
    for (int nh = 0; nh < 2; nh++) {        // two 128-col halves of the 256 tile
        int nb = n0 + nh * 128;
        float acc[8][8];
        #pragma unroll
        for (int i = 0; i < 8; i++)
            #pragma unroll
            for (int j = 0; j < 8; j++) acc[i][j] = 0.f;
        for (int k0 = 0; k0 < K; k0 += 16) {
            for (int idx = tid; idx < 512; idx += 256) {
                int r  = idx >> 2;
                int c4 = idx & 3;
                #pragma unroll
                for (int e = 0; e < 4; e++) {
                    int kk = c4 * 4 + e;
                    size_t ga = (size_t)(m0 + r) * K + k0 + kk;
                    size_t gb = (size_t)(nb + r) * K + k0 + kk;
                    As[kk][r] = __half2float(Ah[ga]) + __half2float(Al[ga]);
                    Bs[kk][r] = __half2float(Bh[gb]) + __half2float(Bl[gb]);
                }
            }
            __syncthreads();
            #pragma unroll
            for (int kk = 0; kk < 16; kk++) {
                float ra[8], rb[8];
                *(float4*)&ra[0] = *(const float4*)&As[kk][trow * 8];
                *(float4*)&ra[4] = *(const float4*)&As[kk][trow * 8 + 4];
                *(float4*)&rb[0] = *(const float4*)&Bs[kk][tcol * 8];
                *(float4*)&rb[4] = *(const float4*)&Bs[kk][tcol * 8 + 4];
                #pragma unroll
                for (int i = 0; i < 8; i++)
                    #pragma unroll
                    for (int j = 0; j < 8; j++)
                        acc[i][j] = fmaf(ra[i], rb[j], acc[i][j]);
            }
            __syncthreads();
        }
        #pragma unroll
        for (int i = 0; i < 8; i++) {
            int m = m0 + trow * 8 + i;
            #pragma unroll
            for (int jj = 0; jj < 8; jj++) {
                int n = nb + tcol * 8 + jj;
                float v = acc[i][jj];
                if (bias) v += bias[n];
                C[(size_t)m * N + n] = v;
            }
        }
        __syncthreads();
    }
#endif
}

// ---------------------------------------------------------------------------
// Tensor-core causal GQA attention, LEAN 2-CTA/SM + split KV tail.
// P uses fp16-hi ONLY (p in (0,1] -> hi carries >=11 bits; PV = 2 passes:
// Ph*Vh + Ph*Vl). QK stays 3-pass (errors there get exponentiated).
//  TMEM: S @0 (128 f32; Ph overlays @0..63 after read) | O @128
// ---------------------------------------------------------------------------
#define ATT_THREADS 128
#define AS_TMEM   0
#define AS_MQK    16
#define AS_MPV    24
#define AS_Q      1024               // Qh 16K | Ql 16K
#define AS_KV     (AS_Q + 32768)     // Kh 16K | Kl 16K | Vh 2x8K | Vl 2x8K
#define AS_TOTAL  (AS_KV + 65536 + 64)   // ~99KB -> 2 CTAs/SM

__global__ __launch_bounds__(ATT_THREADS, 2)
void attn_tc(const __half* __restrict__ QH, const __half* __restrict__ QL,
             const __half* __restrict__ KH, const __half* __restrict__ KL,
             const __half* __restrict__ VTH, const __half* __restrict__ VTL,
             __half* __restrict__ ATH, __half* __restrict__ ATL) {
    extern __shared__ char sm[];
    int tid = threadIdx.x;
    int qb = 15 - (int)blockIdx.x;          // big tiles first
    int hd = blockIdx.y, b = blockIdx.z;
    int khead = hd >> 2;

#if HAS_TCGEN05
    uint32_t sb = smem_u32(sm);
    if (tid == 0) {
        asm volatile("mbarrier.init.shared.b64 [%0], 1;" :: "r"(sb + AS_MQK) : "memory");
        asm volatile("mbarrier.init.shared.b64 [%0], 1;" :: "r"(sb + AS_MPV) : "memory");
    }
    if (tid < 32) {
        asm volatile("tcgen05.alloc.cta_group::1.sync.aligned.shared::cta.b32 [%0], %1;"
                     :: "r"(sb + AS_TMEM), "r"(256u) : "memory");
        asm volatile("tcgen05.relinquish_alloc_permit.cta_group::1.sync.aligned;");
    }
    __syncthreads();
    uint32_t tmem;
    asm volatile("ld.shared.b32 %0, [%1];" : "=r"(tmem) : "r"(sb + AS_TMEM));

    const uint32_t IDQK = (1u << 4) | (16u << 17) | (8u << 24);  // f16 M128 N128
    const uint32_t IDPV = (1u << 4) | (8u  << 17) | (8u << 24);  // f16 M128 N64
    const uint32_t TM_O = 128;

    // ---- Q tile (once): 2048 f4 over 128 threads ----
    #pragma unroll
    for (int i2 = 0; i2 < 8; i2++) {
        int idx = tid + i2 * 128;            // 0..1023
        int r = idx >> 3, c8 = idx & 7;
        uint32_t off = (uint32_t)(r * 128 + c8 * 16);
        off ^= (off >> 3) & 0x70;
        size_t go = (((size_t)(b * Sc + qb * 128 + r)) * NHc + hd) * HDc + c8 * 8;
        *(float4*)(sm + AS_Q + off)         = *(const float4*)(QH + go);
        *(float4*)(sm + AS_Q + 16384 + off) = *(const float4*)(QL + go);
    }

    // K loader: straight to smem (8 f4 pairs per thread)
    auto load_k = [&](int kbase) {
        char* base = sm + AS_KV;
        #pragma unroll
        for (int i2 = 0; i2 < 8; i2++) {             // K: 128 rows x 64 fp16
            int idx = tid + i2 * 128;
            int r = idx >> 3, c8 = idx & 7;
            uint32_t off = (uint32_t)(r * 128 + c8 * 16);
            off ^= (off >> 3) & 0x70;
            size_t go = (((size_t)(b * Sc + kbase + r)) * NKVc + khead) * HDc + c8 * 8;
            *(float4*)(base + off)         = *(const float4*)(KH + go);
            *(float4*)(base + 16384 + off) = *(const float4*)(KL + go);
        }
    };
    // V: register-staged (ldg then sts after the buffer frees)
    auto ldg_v = [&](int kbase, float4* rv) {
        #pragma unroll
        for (int i2 = 0; i2 < 8; i2++) {             // V^T: 64 d-rows x 128 keys
            int idx = tid + i2 * 128;
            int d = idx >> 4, c8 = idx & 15;
            size_t go = ((size_t)(b * NKVc + khead) * HDc + d) * Sc + kbase + c8 * 8;
            rv[i2 * 2 + 0] = *(const float4*)(VTH + go);
            rv[i2 * 2 + 1] = *(const float4*)(VTL + go);
        }
    };
    auto sts_v = [&](const float4* rv) {
        char* base = sm + AS_KV;
        #pragma unroll
        for (int i2 = 0; i2 < 8; i2++) {
            int idx = tid + i2 * 128;
            int d = idx >> 4, c8 = idx & 15;
            int sub = c8 >> 3;
            uint32_t off = (uint32_t)(d * 128 + (c8 & 7) * 16);
            off ^= (off >> 3) & 0x70;
            *(float4*)(base + 32768 + sub * 8192 + off) = rv[i2 * 2 + 0];
            *(float4*)(base + 49152 + sub * 8192 + off) = rv[i2 * 2 + 1];
        }
    };

    // QK for current KV buffer -> S @ tmem, commit MQK
    auto issue_qk = [&]() {
        uint32_t kvb = sb + AS_KV;
        uint64_t qhd = mk_desc(sb + AS_Q);
        uint64_t qld = mk_desc(sb + AS_Q + 16384);
        uint64_t khd = mk_desc(kvb);
        uint64_t kld = mk_desc(kvb + 16384);
        #pragma unroll
        for (int ks = 0; ks < 4; ks++) {
            mma_f16(tmem, qhd + ks * 2, khd + ks * 2, IDQK, ks == 0 ? 0u : 1u);
            mma_f16(tmem, qhd + ks * 2, kld + ks * 2, IDQK, 1u);
            mma_f16(tmem, qld + ks * 2, khd + ks * 2, IDQK, 1u);
        }
        asm volatile(
            "tcgen05.commit.cta_group::1.mbarrier::arrive::one.shared::cluster.b64 [%0];"
            :: "r"(sb + AS_MQK) : "memory");
    };

    {   // prologue: KV(0) fully to smem
        load_k(0);
        float4 rv[16];
        ldg_v(0, rv);
        sts_v(rv);
    }
    __syncthreads();
    if (tid == 0) {
        asm volatile("fence.proxy.async.shared::cta;" ::: "memory");
        issue_qk();
    }

    float m_run = -1e30f, l_run = 0.f;
    uint32_t warp_off = ((uint32_t)(tid >> 5)) << 21;
    int row = tid;

    for (int i = 0; i <= qb; i++) {
        // ---- softmax(i): wait QK(i) ----
        mbar_wait(sb + AS_MQK, i & 1);
        asm volatile("tcgen05.fence::after_thread_sync;" ::: "memory");

        float s[128];
        float mx = m_run;
        #pragma unroll
        for (int ch = 0; ch < 4; ch++) {
            uint32_t r32[32];
            ldtm32(r32, tmem + (uint32_t)ch * 32);
            asm volatile("tcgen05.wait::ld.sync.aligned;" ::: "memory");
            #pragma unroll
            for (int j = 0; j < 32; j++) {
                int key = ch * 32 + j;
                float sv = (i == qb && key > row) ? -1e30f : __uint_as_float(r32[j]);
                s[key] = sv;
                mx = fmaxf(mx, sv);
            }
        }
        float corr = fast_exp2(m_run - mx);
        if (i > 0) {
            bool need = !__all_sync(0xffffffffu, mx == m_run);
            if (need) {
                #pragma unroll
                for (int g = 0; g < 2; g++) {
                    uint32_t o32[32];
                    ldtm32(o32, tmem + TM_O + (uint32_t)g * 32);
                    asm volatile("tcgen05.wait::ld.sync.aligned;" ::: "memory");
                    #pragma unroll
                    for (int j = 0; j < 32; j++)
                        o32[j] = __float_as_uint(__uint_as_float(o32[j]) * corr);
                    sttm32(tmem + TM_O + (uint32_t)g * 32 + warp_off, o32);
                }
            }
        } else {
            corr = 0.f;
        }

        // P = exp2(s - mx); fp16-hi only (p in (0,1]); overlay S cols 0..63
        float sum = 0.f;
        #pragma unroll
        for (int ch = 0; ch < 4; ch++) {
            uint32_t phw[16];
            #pragma unroll
            for (int j = 0; j < 16; j++) {
                float p0 = fast_exp2(s[ch * 32 + j * 2]     - mx);
                float p1 = fast_exp2(s[ch * 32 + j * 2 + 1] - mx);
                sum += p0 + p1;
                __half2 hp = __floats2half2_rn(p0, p1);
                phw[j] = *(uint32_t*)&hp;
            }
            sttm16(tmem + (uint32_t)ch * 16 + warp_off, phw);        // Ph @0..63
        }
        asm volatile("tcgen05.wait::st.sync.aligned;" ::: "memory");
        asm volatile("tcgen05.fence::before_thread_sync;" ::: "memory");

        l_run = l_run * corr + sum;
        m_run = mx;
        __syncthreads();   // all warps' P written

        // ---- PV(i): 2 passes (Ph*Vh + Ph*Vl) ----
        if (tid == 0) {
            asm volatile("tcgen05.fence::after_thread_sync;" ::: "memory");
            uint32_t kvb = sb + AS_KV;
            #pragma unroll
            for (int kk = 0; kk < 8; kk++) {             // 16 keys per step
                int sub = kk >> 2, ks = kk & 3;
                uint64_t vh = mk_desc(kvb + 32768 + (uint32_t)sub * 8192) + ks * 2;
                uint64_t vl = mk_desc(kvb + 49152 + (uint32_t)sub * 8192) + ks * 2;
                uint32_t ah = tmem + (uint32_t)kk * 8;
                mma_f16_ts(tmem + TM_O, ah, vh, IDPV, (i == 0 && kk == 0) ? 0u : 1u);
                mma_f16_ts(tmem + TM_O, ah, vl, IDPV, 1u);
            }
            asm volatile(
                "tcgen05.commit.cta_group::1.mbarrier::arrive::one.shared::cluster.b64 [%0];"
                :: "r"(sb + AS_MPV) : "memory");
        }

        if (i + 1 <= qb) {
            // K(i+1) direct to smem (K(i) consumed by QK(i)); overlaps PV(i).
            load_k((i + 1) * 128);
            // V(i+1) into registers: LDG latency overlaps PV(i).
            float4 rv[16];
            ldg_v((i + 1) * 128, rv);
            mbar_wait(sb + AS_MPV, i & 1);   // V(i) consumed by PV(i)
            sts_v(rv);
            __syncthreads();
            if (tid == 0) {
                asm volatile("fence.proxy.async.shared::cta;" ::: "memory");
                issue_qk();
            }
        } else {
            mbar_wait(sb + AS_MPV, i & 1);
        }
    }

    // ---- epilogue: O/l -> fp16 hi/lo att (PV(qb) already waited) ----
    asm volatile("tcgen05.fence::after_thread_sync;" ::: "memory");
    {
        float inv_l = 1.0f / l_run;
        size_t obase = ((size_t)(b * Sc + qb * 128 + row)) * (NHc * HDc) + (size_t)hd * HDc;
        #pragma unroll
        for (int g = 0; g < 2; g++) {
            uint32_t o32[32];
            ldtm32(o32, tmem + TM_O + (uint32_t)g * 32);
            asm volatile("tcgen05.wait::ld.sync.aligned;" ::: "memory");
            #pragma unroll
            for (int j = 0; j < 32; j += 2) {
                float v0 = __uint_as_float(o32[j])     * inv_l;
                float v1 = __uint_as_float(o32[j + 1]) * inv_l;
                __half h0, l0, h1, l1;
                split_h(v0, h0, l0);
                split_h(v1, h1, l1);
                *(__half2*)(ATH + obase + g * 32 + j) = __halves2half2(h0, h1);
                *(__half2*)(ATL + obase + g * 32 + j) = __halves2half2(l0, l1);
            }
        }
    }
    __syncthreads();
    if (tid < 32) {
        asm volatile("tcgen05.dealloc.cta_group::1.sync.aligned.b32 %0, %1;"
                     :: "r"(tmem), "r"(256u));
    }
#else
    // fp32 flash fallback (plain sm_103 pass only)
    float* Ks = (float*)(sm);
    float* Vs = (float*)(sm + 128 * 64 * 4);
    int row = tid & 127;
    int qi = qb * 128 + row;
    float q[HDc], o[HDc];
    float m = -1e30f, l = 0.f;
    if (tid < 128) {
        #pragma unroll
        for (int d = 0; d < HDc; d++) {
            size_t go = (((size_t)(b * Sc + qi)) * NHc + hd) * HDc + d;
            q[d] = __half2float(QH[go]) + __half2float(QL[go]);
            o[d] = 0.f;
        }
    }
    for (int kt = 0; kt <= qb; kt++) {
        int kbase = kt * 128;
        __syncthreads();
        for (int idx = tid; idx < 128 * 64; idx += ATT_THREADS) {
            int r = idx >> 6, d = idx & 63;
            size_t go = (((size_t)(b * Sc + kbase + r)) * NKVc + khead) * HDc + d;
            Ks[r * 64 + d] = __half2float(KH[go]) + __half2float(KL[go]);
            size_t gv = ((size_t)(b * NKVc + khead) * HDc + d) * Sc + kbase + r;
            Vs[r * 64 + d] = __half2float(VTH[gv]) + __half2float(VTL[gv]);
        }
        __syncthreads();
        if (tid < 128) {
            int kmax = (kt == qb) ? (row + 1) : 128;
            for (int c = 0; c < kmax; c++) {
                float s = 0.f;
                #pragma unroll
                for (int d = 0; d < HDc; d++) s = fmaf(q[d], Ks[c * 64 + d], s);
                float mn = fmaxf(m, s);
                float cf = fast_exp2(m - mn);
                float p  = fast_exp2(s - mn);
                l = l * cf + p;
                #pragma unroll
                for (int d = 0; d < HDc; d++)
                    o[d] = o[d] * cf + p * Vs[c * 64 + d];
                m = mn;
            }
        }
    }
    if (tid < 128) {
        float inv_l = 1.0f / l;
        #pragma unroll
        for (int d = 0; d < HDc; d++) {
            float v = o[d] * inv_l;
            __half h, lo;
            split_h(v, h, lo);
            size_t go = (((size_t)(b * Sc + qi)) * NHc + hd) * HDc + d;
            ATH[go] = h;
            ATL[go] = lo;
        }
    }
#endif
}

// ---------------------------------------------------------------------------
// launch
// ---------------------------------------------------------------------------
extern "C" void kernel_launch(void* const* d_in, const int* in_sizes, int n_in,
                              void* d_out, int out_size) {
    (void)in_sizes; (void)n_in; (void)out_size;
    const float* x   = (const float*)d_in[0];
    const int*   pos = (const int*)  d_in[1];
    const float* Wq  = (const float*)d_in[2];
    const float* bq  = (const float*)d_in[3];
    const float* Wk  = (const float*)d_in[4];
    const float* bk  = (const float*)d_in[5];
    const float* Wv  = (const float*)d_in[6];
    const float* bv  = (const float*)d_in[7];
    const float* Wo  = (const float*)d_in[8];
    float* out = (float*)d_out;

    float *qkv, *cs, *sn, *bc;
    __half *xh, *xl, *qh, *ql, *kh, *kl, *vth, *vtl, *ath, *atl;
    __half *wch, *wcl, *woh, *wol;
    cudaGetSymbolAddress((void**)&qkv, g_qkv);
    cudaGetSymbolAddress((void**)&cs,  g_cos);
    cudaGetSymbolAddress((void**)&sn,  g_sin);
    cudaGetSymbolAddress((void**)&bc,  g_bc);
    cudaGetSymbolAddress((void**)&xh,  g_xh);
    cudaGetSymbolAddress((void**)&xl,  g_xl);
    cudaGetSymbolAddress((void**)&qh,  g_qh);
    cudaGetSymbolAddress((void**)&ql,  g_ql);
    cudaGetSymbolAddress((void**)&kh,  g_kh);
    cudaGetSymbolAddress((void**)&kl,  g_kl);
    cudaGetSymbolAddress((void**)&vth, g_vth);
    cudaGetSymbolAddress((void**)&vtl, g_vtl);
    cudaGetSymbolAddress((void**)&ath, g_ath);
    cudaGetSymbolAddress((void**)&atl, g_atl);
    cudaGetSymbolAddress((void**)&wch, g_wch);
    cudaGetSymbolAddress((void**)&wcl, g_wcl);
    cudaGetSymbolAddress((void**)&woh, g_woh);
    cudaGetSymbolAddress((void**)&wol, g_wol);

    cudaFuncSetAttribute(tc_gemm, cudaFuncAttributeMaxDynamicSharedMemorySize, SM_GTOTAL);
    cudaFuncSetAttribute(attn_tc, cudaFuncAttributeMaxDynamicSharedMemorySize, AS_TOTAL);

    const float SCALE = 0.125f * 1.4426950408889634f;
    dim3 tb(32, 8);

    // 0) operand prep
    xsplit_kernel<<<(MQ * Hc / 4 + 255) / 256, 256>>>(x, xh, xl, MQ * Hc / 4);
    wconv_kernel<<<dim3(64, 64), tb>>>(Wq, wch,                       wcl,                       2048, 2048);
    wconv_kernel<<<dim3(16, 64), tb>>>(Wk, wch + (size_t)2048 * 2048, wcl + (size_t)2048 * 2048, 2048, 512);
    wconv_kernel<<<dim3(16, 64), tb>>>(Wv, wch + (size_t)2560 * 2048, wcl + (size_t)2560 * 2048, 2048, 512);
    wconv_kernel<<<dim3(64, 64), tb>>>(Wo, woh, wol, 2048, 2048);
    bcat_kernel<<<12, 256>>>(bq, bk, bv, bc);
    cossin_kernel<<<(MQ * HDc + 255) / 256, 256>>>(pos, cs, sn);

    // 1) fused QKV projection (128x256 tiles)
    tc_gemm<<<dim3(NQKV / 256, MQ / 128), GEMM_THREADS, SM_GTOTAL>>>(
        xh, xl, wch, wcl, bc, qkv, NQKV, Hc);

    // 2) RoPE + split; V transpose + split
    rope_split_kernel<<<(MQ * NHc * 32 + 255) / 256, 256>>>(qkv, 0,    cs, sn, qh, ql, NHc,  SCALE, MQ * NHc * 32);
    rope_split_kernel<<<(MQ * NKVc * 32 + 255) / 256, 256>>>(qkv, 2048, cs, sn, kh, kl, NKVc, 1.0f,  MQ * NKVc * 32);
    vtrans_kernel<<<dim3(Sc / 32, HDc / 32, Bc * NKVc), tb>>>(qkv, vth, vtl);

    // 3) tensor-core causal GQA attention (lean 2-CTA/SM, P hi-only PV)
    attn_tc<<<dim3(16, NHc, Bc), ATT_THREADS, AS_TOTAL>>>(qh, ql, kh, kl, vth, vtl, ath, atl);

    // 4) output projection (128x256 tiles)
    tc_gemm<<<dim3(2048 / 256, MQ / 128), GEMM_THREADS, SM_GTOTAL>>>(
        ath, atl, woh, wol, nullptr, out, 2048, Hc);
}